// round 1
// baseline (speedup 1.0000x reference)
#include <cuda_runtime.h>
#include <math.h>

#define Bq 8
#define Nn 2048
#define Cc 256
#define Ee 32768
#define TOT (Bq*Nn*Cc)      // 4194304
#define Mr  (Bq*Nn)         // 16384
#define RB  512

// Persistent scratch (device globals; no allocations allowed)
__device__ float g_h[TOT];
__device__ float g_hn[TOT];
__device__ float g_tx1[TOT];
__device__ float g_tx2[TOT];
__device__ float g_deg[Nn];
__device__ float g_norm[Ee];
__device__ float g_psum[RB];
__device__ float g_psq[RB];
__device__ float g_stats[2];   // mean, rstd

// ---------------- init ----------------
__global__ void copy_init(const float* __restrict__ x) {
    int i = blockIdx.x * 256 + threadIdx.x;          // over TOT/4
    ((float4*)g_h)[i] = ((const float4*)x)[i];
}

// ---------------- global LayerNorm ----------------
__global__ void reduce_partial() {
    int tid = blockIdx.x * blockDim.x + threadIdx.x;
    int stride = gridDim.x * blockDim.x;
    const float4* x4 = (const float4*)g_h;
    float s = 0.f, q = 0.f;
    for (int i = tid; i < TOT / 4; i += stride) {
        float4 v = x4[i];
        s += (v.x + v.y) + (v.z + v.w);
        q += v.x * v.x + v.y * v.y + v.z * v.z + v.w * v.w;
    }
    __shared__ float ss[256], sq[256];
    ss[threadIdx.x] = s; sq[threadIdx.x] = q;
    __syncthreads();
    for (int o = 128; o > 0; o >>= 1) {
        if (threadIdx.x < o) { ss[threadIdx.x] += ss[threadIdx.x + o]; sq[threadIdx.x] += sq[threadIdx.x + o]; }
        __syncthreads();
    }
    if (threadIdx.x == 0) { g_psum[blockIdx.x] = ss[0]; g_psq[blockIdx.x] = sq[0]; }
}

__global__ void reduce_final() {
    __shared__ double ss[RB], sq[RB];
    int t = threadIdx.x;
    ss[t] = (double)g_psum[t]; sq[t] = (double)g_psq[t];
    __syncthreads();
    for (int o = RB / 2; o > 0; o >>= 1) {
        if (t < o) { ss[t] += ss[t + o]; sq[t] += sq[t + o]; }
        __syncthreads();
    }
    if (t == 0) {
        double mean = ss[0] / (double)TOT;
        double var  = sq[0] / (double)TOT - mean * mean;
        g_stats[0] = (float)mean;
        g_stats[1] = rsqrtf((float)var + 1e-5f);
    }
}

// hn = (h-m)*r ; if cheb: tx2 = -hn, tx1 = 0  (fused to save passes)
__global__ void normalize_k(int cheb) {
    float m = g_stats[0], r = g_stats[1];
    int i = blockIdx.x * 256 + threadIdx.x;          // over TOT/4
    float4 v = ((const float4*)g_h)[i];
    float4 o;
    o.x = (v.x - m) * r; o.y = (v.y - m) * r; o.z = (v.z - m) * r; o.w = (v.w - m) * r;
    ((float4*)g_hn)[i] = o;
    if (cheb) {
        float4 t; t.x = -o.x; t.y = -o.y; t.z = -o.z; t.w = -o.w;
        ((float4*)g_tx2)[i] = t;
        ((float4*)g_tx1)[i] = make_float4(0.f, 0.f, 0.f, 0.f);
    }
}

// ---------------- edge norm ----------------
__global__ void zero_deg() {
    int i = blockIdx.x * 256 + threadIdx.x;
    if (i < Nn) g_deg[i] = 0.f;
}

__global__ void deg_k(const int* __restrict__ row, const int* __restrict__ col,
                      const float* __restrict__ w) {
    int e = blockIdx.x * 256 + threadIdx.x;
    int r = row[e], c = col[e];
    float we = (r == c) ? 0.f : w[e];
    atomicAdd(&g_deg[r], we);
}

__global__ void norm_k(const int* __restrict__ row, const int* __restrict__ col,
                       const float* __restrict__ w) {
    int e = blockIdx.x * 256 + threadIdx.x;
    int r = row[e], c = col[e];
    float we = (r == c) ? 0.f : w[e];
    float dr = g_deg[r], dc = g_deg[c];
    float ir = dr > 0.f ? rsqrtf(fmaxf(dr, 1e-12f)) : 0.f;
    float ic = dc > 0.f ? rsqrtf(fmaxf(dc, 1e-12f)) : 0.f;
    g_norm[e] = -(ir * we * ic);
}

// ---------------- sparse propagation (scatter) ----------------
// first=1: tx1 += norm * hn[row] ; first=0: tx2 += 2*norm * tx1[row]
__global__ void prop_k(const int* __restrict__ row, const int* __restrict__ col, int first) {
    int e = blockIdx.x;
    int r = row[e], c = col[e];
    float nm = g_norm[e] * (first ? 1.f : 2.f);
    if (nm == 0.f) return;
    const float* src = first ? g_hn : g_tx1;
    float* dst = first ? g_tx1 : g_tx2;
    for (int i = threadIdx.x; i < Bq * (Cc / 4); i += 256) {
        int b = i >> 6, c4 = i & 63;
        float4 v = __ldg(&((const float4*)(src + (b * Nn + r) * Cc))[c4]);
        float* d = dst + (b * Nn + c) * Cc + c4 * 4;
        asm volatile("red.global.add.v4.f32 [%0], {%1,%2,%3,%4};"
                     :: "l"(d), "f"(nm * v.x), "f"(nm * v.y), "f"(nm * v.z), "f"(nm * v.w)
                     : "memory");
    }
}

// ---------------- GEMMs ----------------
// h[m,:] += hn@W0 + tx1@W1 + tx2@W2 + bias   (W3 = [W0;W1;W2] contiguous)
__global__ __launch_bounds__(256, 2) void cheb_gemm(const float* __restrict__ W3,
                                                    const float* __restrict__ bias) {
    __shared__ float As[16][65];
    __shared__ float Ws[16][64];
    int m0 = blockIdx.x * 64, n0 = blockIdx.y * 64;
    int tid = threadIdx.x;
    int tr = tid >> 4, tc = tid & 15;
    const int ar = tid >> 2;            // 0..63
    const int ak = (tid & 3) << 2;      // 0,4,8,12
    const int wr = tid >> 4;            // 0..15
    const int wn = (tid & 15) << 2;     // 0..60
    float acc[4][4] = {};
    for (int seg = 0; seg < 3; seg++) {
        const float* A = seg == 0 ? g_hn : (seg == 1 ? g_tx1 : g_tx2);
        const float* Wp = W3 + seg * Cc * Cc;
        for (int k0 = 0; k0 < Cc; k0 += 16) {
            float4 av = *(const float4*)(A + (m0 + ar) * Cc + k0 + ak);
            float4 wv = *(const float4*)(Wp + (k0 + wr) * Cc + n0 + wn);
            As[ak + 0][ar] = av.x; As[ak + 1][ar] = av.y;
            As[ak + 2][ar] = av.z; As[ak + 3][ar] = av.w;
            *(float4*)&Ws[wr][wn] = wv;
            __syncthreads();
            #pragma unroll
            for (int k = 0; k < 16; k++) {
                float a[4], bb[4];
                #pragma unroll
                for (int i = 0; i < 4; i++) a[i] = As[k][tr * 4 + i];
                #pragma unroll
                for (int j = 0; j < 4; j++) bb[j] = Ws[k][tc * 4 + j];
                #pragma unroll
                for (int i = 0; i < 4; i++)
                    #pragma unroll
                    for (int j = 0; j < 4; j++)
                        acc[i][j] += a[i] * bb[j];
            }
            __syncthreads();
        }
    }
    #pragma unroll
    for (int i = 0; i < 4; i++) {
        int m = m0 + tr * 4 + i;
        float4* hp = (float4*)(g_h + m * Cc + n0 + tc * 4);
        float4 hv = *hp;
        const float4 bv = *(const float4*)(bias + n0 + tc * 4);
        hv.x += acc[i][0] + bv.x;
        hv.y += acc[i][1] + bv.y;
        hv.z += acc[i][2] + bv.z;
        hv.w += acc[i][3] + bv.w;
        *hp = hv;
    }
}

__device__ __forceinline__ float gelu_exact(float v) {
    return 0.5f * v * (1.f + erff(v * 0.70710678118654752f));
}

// h[m,:] += gelu(hn@W + bias)
__global__ __launch_bounds__(256, 2) void mlp_gemm(const float* __restrict__ W,
                                                   const float* __restrict__ bias) {
    __shared__ float As[16][65];
    __shared__ float Ws[16][64];
    int m0 = blockIdx.x * 64, n0 = blockIdx.y * 64;
    int tid = threadIdx.x;
    int tr = tid >> 4, tc = tid & 15;
    const int ar = tid >> 2;
    const int ak = (tid & 3) << 2;
    const int wr = tid >> 4;
    const int wn = (tid & 15) << 2;
    float acc[4][4] = {};
    for (int k0 = 0; k0 < Cc; k0 += 16) {
        float4 av = *(const float4*)(g_hn + (m0 + ar) * Cc + k0 + ak);
        float4 wv = *(const float4*)(W + (k0 + wr) * Cc + n0 + wn);
        As[ak + 0][ar] = av.x; As[ak + 1][ar] = av.y;
        As[ak + 2][ar] = av.z; As[ak + 3][ar] = av.w;
        *(float4*)&Ws[wr][wn] = wv;
        __syncthreads();
        #pragma unroll
        for (int k = 0; k < 16; k++) {
            float a[4], bb[4];
            #pragma unroll
            for (int i = 0; i < 4; i++) a[i] = As[k][tr * 4 + i];
            #pragma unroll
            for (int j = 0; j < 4; j++) bb[j] = Ws[k][tc * 4 + j];
            #pragma unroll
            for (int i = 0; i < 4; i++)
                #pragma unroll
                for (int j = 0; j < 4; j++)
                    acc[i][j] += a[i] * bb[j];
        }
        __syncthreads();
    }
    #pragma unroll
    for (int i = 0; i < 4; i++) {
        int m = m0 + tr * 4 + i;
        float4* hp = (float4*)(g_h + m * Cc + n0 + tc * 4);
        float4 hv = *hp;
        const float4 bv = *(const float4*)(bias + n0 + tc * 4);
        hv.x += gelu_exact(acc[i][0] + bv.x);
        hv.y += gelu_exact(acc[i][1] + bv.y);
        hv.z += gelu_exact(acc[i][2] + bv.z);
        hv.w += gelu_exact(acc[i][3] + bv.w);
        *hp = hv;
    }
}

// ---------------- final mean over nodes ----------------
__global__ void zero_out(float* __restrict__ out) {
    int i = blockIdx.x * 256 + threadIdx.x;
    if (i < Bq * Cc) out[i] = 0.f;
}

__global__ void mean_k(float* __restrict__ out) {
    int b = blockIdx.x, chunk = blockIdx.y;
    int c = threadIdx.x;
    float s = 0.f;
    int nb = chunk * 128;
    const float* base = g_h + (size_t)b * Nn * Cc + c;
    for (int n = nb; n < nb + 128; n++) s += base[(size_t)n * Cc];
    atomicAdd(&out[b * Cc + c], s * (1.f / (float)Nn));
}

// ---------------- launch ----------------
extern "C" void kernel_launch(void* const* d_in, const int* in_sizes, int n_in,
                              void* d_out, int out_size) {
    const float* nf = (const float*)d_in[0];   // node_feature [8,2048,256]
    const float* ew = (const float*)d_in[1];   // edge_weight  [3,32768]
    const float* cw = (const float*)d_in[2];   // cheb_w [3,3,256,256]
    const float* cb = (const float*)d_in[3];   // cheb_b [3,256]
    const float* mw = (const float*)d_in[4];   // mlp_w  [3,256,256]
    const float* mb = (const float*)d_in[5];   // mlp_b  [3,256]
    const int*   ei = (const int*)d_in[6];     // edge_index [3,2,32768]
    float* out = (float*)d_out;                // [8,256]

    copy_init<<<TOT / 1024, 256>>>(nf);
    for (int l = 0; l < 3; l++) {
        const int* row = ei + l * 2 * Ee;
        const int* col = row + Ee;
        const float* w = ew + l * Ee;

        // LN -> hn (and tx2=-hn, tx1=0)
        reduce_partial<<<RB, 256>>>();
        reduce_final<<<1, RB>>>();
        normalize_k<<<TOT / 1024, 256>>>(1);

        // edge normalization
        zero_deg<<<8, 256>>>();
        deg_k<<<Ee / 256, 256>>>(row, col, w);
        norm_k<<<Ee / 256, 256>>>(row, col, w);

        // Chebyshev recursion props
        prop_k<<<Ee, 256>>>(row, col, 1);   // tx1 = prop(hn)
        prop_k<<<Ee, 256>>>(row, col, 0);   // tx2 = 2*prop(tx1) - hn

        // fused K-GEMM + bias + residual (in-place on h)
        cheb_gemm<<<dim3(Mr / 64, Cc / 64), 256>>>(cw + l * 3 * Cc * Cc, cb + l * Cc);

        // LN -> hn
        reduce_partial<<<RB, 256>>>();
        reduce_final<<<1, RB>>>();
        normalize_k<<<TOT / 1024, 256>>>(0);

        // MLP + GELU + residual (in-place on h)
        mlp_gemm<<<dim3(Mr / 64, Cc / 64), 256>>>(mw + l * Cc * Cc, mb + l * Cc);
    }
    zero_out<<<8, 256>>>(out);
    mean_k<<<dim3(Bq, 16), 256>>>(out);
}

// round 3
// speedup vs baseline: 1.2751x; 1.2751x over previous
#include <cuda_runtime.h>
#include <math.h>

#define Bq 8
#define Nn 2048
#define Cc 256
#define Ee 32768
#define TOT (Bq*Nn*Cc)      // 4194304
#define Mr  (Bq*Nn)         // 16384
#define RB  512

// Persistent scratch (device globals; no allocations allowed)
__device__ float g_h[TOT];
__device__ float g_hn[TOT];
__device__ float g_tx1[TOT];
__device__ float g_tx2[TOT];
__device__ float g_deg[Nn];
__device__ float g_norm[Ee];
__device__ float g_psum[RB];
__device__ float g_psq[RB];
__device__ float g_stats[2];   // mean, rstd
// CSR by destination (col)
__device__ int g_cnt[Nn];
__device__ int g_off[Nn + 1];
__device__ int g_ptr[Nn];
__device__ int g_csr[Ee];

// ---------------- init ----------------
__global__ void copy_init(const float* __restrict__ x) {
    int i = blockIdx.x * 256 + threadIdx.x;          // over TOT/4
    ((float4*)g_h)[i] = ((const float4*)x)[i];
}

// ---------------- global LayerNorm ----------------
__global__ void reduce_partial() {
    int tid = blockIdx.x * blockDim.x + threadIdx.x;
    int stride = gridDim.x * blockDim.x;
    const float4* x4 = (const float4*)g_h;
    float s = 0.f, q = 0.f;
    for (int i = tid; i < TOT / 4; i += stride) {
        float4 v = x4[i];
        s += (v.x + v.y) + (v.z + v.w);
        q += v.x * v.x + v.y * v.y + v.z * v.z + v.w * v.w;
    }
    __shared__ float ss[256], sq[256];
    ss[threadIdx.x] = s; sq[threadIdx.x] = q;
    __syncthreads();
    for (int o = 128; o > 0; o >>= 1) {
        if (threadIdx.x < o) { ss[threadIdx.x] += ss[threadIdx.x + o]; sq[threadIdx.x] += sq[threadIdx.x + o]; }
        __syncthreads();
    }
    if (threadIdx.x == 0) { g_psum[blockIdx.x] = ss[0]; g_psq[blockIdx.x] = sq[0]; }
}

__global__ void reduce_final() {
    __shared__ double ss[RB], sq[RB];
    int t = threadIdx.x;
    ss[t] = (double)g_psum[t]; sq[t] = (double)g_psq[t];
    __syncthreads();
    for (int o = RB / 2; o > 0; o >>= 1) {
        if (t < o) { ss[t] += ss[t + o]; sq[t] += sq[t + o]; }
        __syncthreads();
    }
    if (t == 0) {
        double mean = ss[0] / (double)TOT;
        double var  = sq[0] / (double)TOT - mean * mean;
        g_stats[0] = (float)mean;
        g_stats[1] = rsqrtf((float)var + 1e-5f);
    }
}

// hn = (h-m)*r
__global__ void normalize_k() {
    float m = g_stats[0], r = g_stats[1];
    int i = blockIdx.x * 256 + threadIdx.x;          // over TOT/4
    float4 v = ((const float4*)g_h)[i];
    float4 o;
    o.x = (v.x - m) * r; o.y = (v.y - m) * r; o.z = (v.z - m) * r; o.w = (v.w - m) * r;
    ((float4*)g_hn)[i] = o;
}

// ---------------- edge norm + CSR build ----------------
__global__ void zero_small() {
    int i = blockIdx.x * 256 + threadIdx.x;
    if (i < Nn) { g_deg[i] = 0.f; g_cnt[i] = 0; }
}

__global__ void deg_count_k(const int* __restrict__ row, const int* __restrict__ col,
                            const float* __restrict__ w) {
    int e = blockIdx.x * 256 + threadIdx.x;
    int r = row[e], c = col[e];
    float we = (r == c) ? 0.f : w[e];
    atomicAdd(&g_deg[r], we);
    atomicAdd(&g_cnt[c], 1);
}

__global__ void scan_k() {
    __shared__ int chunk[256];
    int t = threadIdx.x;
    int base = t * 8;
    int s = 0;
    #pragma unroll
    for (int i = 0; i < 8; i++) s += g_cnt[base + i];
    chunk[t] = s;
    __syncthreads();
    // inclusive scan (Hillis-Steele)
    for (int o = 1; o < 256; o <<= 1) {
        int v = (t >= o) ? chunk[t - o] : 0;
        __syncthreads();
        chunk[t] += v;
        __syncthreads();
    }
    int run = chunk[t] - s;   // exclusive prefix of this chunk
    #pragma unroll
    for (int i = 0; i < 8; i++) {
        g_off[base + i] = run;
        g_ptr[base + i] = run;
        run += g_cnt[base + i];
    }
    if (t == 255) g_off[Nn] = run;
}

__global__ void norm_scatter_k(const int* __restrict__ row, const int* __restrict__ col,
                               const float* __restrict__ w) {
    int e = blockIdx.x * 256 + threadIdx.x;
    int r = row[e], c = col[e];
    float we = (r == c) ? 0.f : w[e];
    float dr = g_deg[r], dc = g_deg[c];
    float ir = dr > 0.f ? rsqrtf(fmaxf(dr, 1e-12f)) : 0.f;
    float ic = dc > 0.f ? rsqrtf(fmaxf(dc, 1e-12f)) : 0.f;
    g_norm[e] = -(ir * we * ic);
    int pos = atomicAdd(&g_ptr[c], 1);
    g_csr[pos] = e;
}

// ---------------- sparse propagation (gather, no atomics) ----------------
// mode1: tx1[n] = sum_e norm_e * hn[row_e]
// mode2: tx2[n] = 2*sum_e norm_e * tx1[row_e] - hn[n]
__global__ void prop_gather(const int* __restrict__ row, int first) {
    int n = blockIdx.x, b = blockIdx.y;
    int t = threadIdx.x;                    // 64 threads, float4 each
    int s = g_off[n], e = g_off[n + 1];
    const float4* src = (const float4*)(first ? g_hn : g_tx1);
    float4 acc = make_float4(0.f, 0.f, 0.f, 0.f);
    __shared__ int   sr[64];
    __shared__ float sn[64];
    for (int base = s; base < e; base += 64) {
        int cnt = min(64, e - base);
        if (t < cnt) {
            int eid = g_csr[base + t];
            sr[t] = row[eid];
            sn[t] = g_norm[eid];
        }
        __syncthreads();
        for (int j = 0; j < cnt; j++) {
            float nm = sn[j];
            float4 v = __ldg(&src[(size_t)(b * Nn + sr[j]) * 64 + t]);
            acc.x += nm * v.x; acc.y += nm * v.y; acc.z += nm * v.z; acc.w += nm * v.w;
        }
        __syncthreads();
    }
    size_t di = (size_t)(b * Nn + n) * 64 + t;
    if (first) {
        ((float4*)g_tx1)[di] = acc;
    } else {
        float4 hv = ((const float4*)g_hn)[di];
        float4 o;
        o.x = 2.f * acc.x - hv.x; o.y = 2.f * acc.y - hv.y;
        o.z = 2.f * acc.z - hv.z; o.w = 2.f * acc.w - hv.w;
        ((float4*)g_tx2)[di] = o;
    }
}

// ---------------- GEMMs: 128x64 tile, 8x4 per thread, double-buffered ----------------
#define BM 128
#define BN 64
#define BK 16
#define APAD 132

__device__ __forceinline__ float gelu_exact(float v) {
    return 0.5f * v * (1.f + erff(v * 0.70710678118654752f));
}

// mode 0: h += (hn@W0 + tx1@W1 + tx2@W2) + bias     (W = [W0;W1;W2], T=48 tiles)
// mode 1: h += gelu(hn@W + bias)                    (T=16 tiles)
template<int MODE>
__global__ __launch_bounds__(256, 2) void big_gemm(const float* __restrict__ W,
                                                   const float* __restrict__ bias) {
    __shared__ float As[2][BK][APAD];
    __shared__ float Ws[2][BK][BN];
    const int m0 = blockIdx.x * BM, n0 = blockIdx.y * BN;
    const int tid = threadIdx.x;
    const int tr = tid >> 4;             // 0..15 -> 8 rows each
    const int tc = tid & 15;             // 0..15 -> 4 cols each
    // A-load indices: rows tid/4 and tid/4+64, k = (tid&3)*4
    const int alr = tid >> 2;
    const int alk = (tid & 3) << 2;
    // W-load indices
    const int wlr = tid >> 4;
    const int wln = (tid & 15) << 2;

    const int T = (MODE == 0) ? 48 : 16;
    const float* srcs[3] = { g_hn, g_tx1, g_tx2 };

    float acc[8][4] = {};

    // prologue: load tile 0
    {
        const float* A = (MODE == 0) ? srcs[0] : g_hn;
        float4 a0 = *(const float4*)(A + (size_t)(m0 + alr) * Cc + alk);
        float4 a1 = *(const float4*)(A + (size_t)(m0 + 64 + alr) * Cc + alk);
        float4 wv = *(const float4*)(W + (size_t)wlr * Cc + n0 + wln);
        As[0][alk + 0][alr] = a0.x; As[0][alk + 1][alr] = a0.y;
        As[0][alk + 2][alr] = a0.z; As[0][alk + 3][alr] = a0.w;
        As[0][alk + 0][64 + alr] = a1.x; As[0][alk + 1][64 + alr] = a1.y;
        As[0][alk + 2][64 + alr] = a1.z; As[0][alk + 3][64 + alr] = a1.w;
        *(float4*)&Ws[0][wlr][wln] = wv;
    }
    __syncthreads();

    for (int t = 0; t < T; t++) {
        int cur = t & 1;
        float4 a0, a1, wv;
        if (t + 1 < T) {
            int nt = t + 1;
            int seg = nt >> 4;
            int k0 = (nt & 15) << 4;
            const float* A = (MODE == 0) ? srcs[seg] : g_hn;
            const float* Wp = W + (size_t)(MODE == 0 ? seg : 0) * Cc * Cc;
            a0 = *(const float4*)(A + (size_t)(m0 + alr) * Cc + k0 + alk);
            a1 = *(const float4*)(A + (size_t)(m0 + 64 + alr) * Cc + k0 + alk);
            wv = *(const float4*)(Wp + (size_t)(k0 + wlr) * Cc + n0 + wln);
        }
        #pragma unroll
        for (int k = 0; k < BK; k++) {
            float a[8], bb[4];
            *(float4*)&a[0] = *(const float4*)&As[cur][k][tr * 8];
            *(float4*)&a[4] = *(const float4*)&As[cur][k][tr * 8 + 4];
            *(float4*)&bb[0] = *(const float4*)&Ws[cur][k][tc * 4];
            #pragma unroll
            for (int i = 0; i < 8; i++)
                #pragma unroll
                for (int j = 0; j < 4; j++)
                    acc[i][j] += a[i] * bb[j];
        }
        if (t + 1 < T) {
            int nxt = (t + 1) & 1;
            As[nxt][alk + 0][alr] = a0.x; As[nxt][alk + 1][alr] = a0.y;
            As[nxt][alk + 2][alr] = a0.z; As[nxt][alk + 3][alr] = a0.w;
            As[nxt][alk + 0][64 + alr] = a1.x; As[nxt][alk + 1][64 + alr] = a1.y;
            As[nxt][alk + 2][64 + alr] = a1.z; As[nxt][alk + 3][64 + alr] = a1.w;
            *(float4*)&Ws[nxt][wlr][wln] = wv;
            __syncthreads();
        }
    }

    const float4 bv = *(const float4*)(bias + n0 + tc * 4);
    #pragma unroll
    for (int i = 0; i < 8; i++) {
        int m = m0 + tr * 8 + i;
        float4* hp = (float4*)(g_h + (size_t)m * Cc + n0 + tc * 4);
        float4 hv = *hp;
        if (MODE == 0) {
            hv.x += acc[i][0] + bv.x;
            hv.y += acc[i][1] + bv.y;
            hv.z += acc[i][2] + bv.z;
            hv.w += acc[i][3] + bv.w;
        } else {
            hv.x += gelu_exact(acc[i][0] + bv.x);
            hv.y += gelu_exact(acc[i][1] + bv.y);
            hv.z += gelu_exact(acc[i][2] + bv.z);
            hv.w += gelu_exact(acc[i][3] + bv.w);
        }
        *hp = hv;
    }
}

// ---------------- final mean over nodes ----------------
__global__ void zero_out(float* __restrict__ out) {
    int i = blockIdx.x * 256 + threadIdx.x;
    if (i < Bq * Cc) out[i] = 0.f;
}

__global__ void mean_k(float* __restrict__ out) {
    int b = blockIdx.x, chunk = blockIdx.y;
    int c = threadIdx.x;
    float s = 0.f;
    int nb = chunk * 128;
    const float* base = g_h + (size_t)b * Nn * Cc + c;
    for (int n = nb; n < nb + 128; n++) s += base[(size_t)n * Cc];
    atomicAdd(&out[b * Cc + c], s * (1.f / (float)Nn));
}

// ---------------- launch ----------------
extern "C" void kernel_launch(void* const* d_in, const int* in_sizes, int n_in,
                              void* d_out, int out_size) {
    const float* nf = (const float*)d_in[0];   // node_feature [8,2048,256]
    const float* ew = (const float*)d_in[1];   // edge_weight  [3,32768]
    const float* cw = (const float*)d_in[2];   // cheb_w [3,3,256,256]
    const float* cb = (const float*)d_in[3];   // cheb_b [3,256]
    const float* mw = (const float*)d_in[4];   // mlp_w  [3,256,256]
    const float* mb = (const float*)d_in[5];   // mlp_b  [3,256]
    const int*   ei = (const int*)d_in[6];     // edge_index [3,2,32768]
    float* out = (float*)d_out;                // [8,256]

    copy_init<<<TOT / 1024, 256>>>(nf);
    for (int l = 0; l < 3; l++) {
        const int* row = ei + l * 2 * Ee;
        const int* col = row + Ee;
        const float* w = ew + l * Ee;

        // LN -> hn
        reduce_partial<<<RB, 256>>>();
        reduce_final<<<1, RB>>>();
        normalize_k<<<TOT / 1024, 256>>>();

        // edge normalization + CSR (by col) build
        zero_small<<<8, 256>>>();
        deg_count_k<<<Ee / 256, 256>>>(row, col, w);
        scan_k<<<1, 256>>>();
        norm_scatter_k<<<Ee / 256, 256>>>(row, col, w);

        // Chebyshev recursion props (gather, no atomics)
        prop_gather<<<dim3(Nn, Bq), 64>>>(row, 1);   // tx1 = prop(hn)
        prop_gather<<<dim3(Nn, Bq), 64>>>(row, 0);   // tx2 = 2*prop(tx1) - hn

        // fused K-GEMM + bias + residual (in-place on h)
        big_gemm<0><<<dim3(Mr / BM, Cc / BN), 256>>>(cw + (size_t)l * 3 * Cc * Cc, cb + l * Cc);

        // LN -> hn
        reduce_partial<<<RB, 256>>>();
        reduce_final<<<1, RB>>>();
        normalize_k<<<TOT / 1024, 256>>>();

        // MLP + GELU + residual (in-place on h)
        big_gemm<1><<<dim3(Mr / BM, Cc / BN), 256>>>(mw + (size_t)l * Cc * Cc, mb + l * Cc);
    }
    zero_out<<<8, 256>>>(out);
    mean_k<<<dim3(Bq, 16), 256>>>(out);
}

// round 5
// speedup vs baseline: 1.6184x; 1.2693x over previous
#include <cuda_runtime.h>
#include <cuda_bf16.h>
#include <math.h>
#include <stdint.h>

#define Bq 8
#define Nn 2048
#define Cc 256
#define Ee 32768
#define TOT (Bq*Nn*Cc)      // 4194304
#define Mr  (Bq*Nn)         // 16384
#define RB  512

typedef __nv_bfloat16 bf16;

// Persistent scratch (device globals; no allocations allowed)
__device__ __align__(16) float g_h[TOT];
__device__ __align__(16) float g_hn[TOT];
__device__ __align__(16) float g_tx1[TOT];
__device__ __align__(16) bf16  g_hn_h[TOT],  g_hn_l[TOT];
__device__ __align__(16) bf16  g_tx1_h[TOT], g_tx1_l[TOT];
__device__ __align__(16) bf16  g_tx2_h[TOT], g_tx2_l[TOT];
__device__ __align__(16) bf16  g_wch_h[3*3*Cc*Cc], g_wch_l[3*3*Cc*Cc];
__device__ __align__(16) bf16  g_wml_h[3*Cc*Cc],   g_wml_l[3*Cc*Cc];
__device__ float g_deg[Nn];
__device__ float g_norm[Ee];
__device__ float g_psum[RB];
__device__ float g_psq[RB];
__device__ float g_stats[2];   // mean, rstd
// CSR by destination (col)
__device__ int g_cnt[Nn];
__device__ int g_off[Nn + 1];
__device__ int g_ptr[Nn];
__device__ int g_csr[Ee];

__device__ __forceinline__ void split2(float x, bf16& h, bf16& l) {
    h = __float2bfloat16(x);
    l = __float2bfloat16(x - __bfloat162float(h));
}

// ---------------- init ----------------
__global__ void copy_init(const float* __restrict__ x) {
    int i = blockIdx.x * 256 + threadIdx.x;          // over TOT/4
    ((float4*)g_h)[i] = ((const float4*)x)[i];
}

// split weights once per launch
__global__ void split_w(const float* __restrict__ cw, const float* __restrict__ mw) {
    int i = blockIdx.x * 256 + threadIdx.x;
    int NC = 3 * 3 * Cc * Cc;
    if (i < NC) split2(cw[i], g_wch_h[i], g_wch_l[i]);
    if (i < 3 * Cc * Cc) split2(mw[i], g_wml_h[i], g_wml_l[i]);
}

// ---------------- global LayerNorm ----------------
__global__ void reduce_partial() {
    int tid = blockIdx.x * blockDim.x + threadIdx.x;
    int stride = gridDim.x * blockDim.x;
    const float4* x4 = (const float4*)g_h;
    float s = 0.f, q = 0.f;
    for (int i = tid; i < TOT / 4; i += stride) {
        float4 v = x4[i];
        s += (v.x + v.y) + (v.z + v.w);
        q += v.x * v.x + v.y * v.y + v.z * v.z + v.w * v.w;
    }
    __shared__ float ss[256], sq[256];
    ss[threadIdx.x] = s; sq[threadIdx.x] = q;
    __syncthreads();
    for (int o = 128; o > 0; o >>= 1) {
        if (threadIdx.x < o) { ss[threadIdx.x] += ss[threadIdx.x + o]; sq[threadIdx.x] += sq[threadIdx.x + o]; }
        __syncthreads();
    }
    if (threadIdx.x == 0) { g_psum[blockIdx.x] = ss[0]; g_psq[blockIdx.x] = sq[0]; }
}

__global__ void reduce_final() {
    __shared__ double ss[RB], sq[RB];
    int t = threadIdx.x;
    ss[t] = (double)g_psum[t]; sq[t] = (double)g_psq[t];
    __syncthreads();
    for (int o = RB / 2; o > 0; o >>= 1) {
        if (t < o) { ss[t] += ss[t + o]; sq[t] += sq[t + o]; }
        __syncthreads();
    }
    if (t == 0) {
        double mean = ss[0] / (double)TOT;
        double var  = sq[0] / (double)TOT - mean * mean;
        g_stats[0] = (float)mean;
        g_stats[1] = rsqrtf((float)var + 1e-5f);
    }
}

// hn = (h-m)*r ; also emit bf16 hi/lo split
__global__ void normalize_k() {
    float m = g_stats[0], r = g_stats[1];
    int i = blockIdx.x * 256 + threadIdx.x;          // over TOT/4
    float4 v = ((const float4*)g_h)[i];
    float4 o;
    o.x = (v.x - m) * r; o.y = (v.y - m) * r; o.z = (v.z - m) * r; o.w = (v.w - m) * r;
    ((float4*)g_hn)[i] = o;
    __nv_bfloat162 h0, h1, l0, l1;
    split2(o.x, h0.x, l0.x); split2(o.y, h0.y, l0.y);
    split2(o.z, h1.x, l1.x); split2(o.w, h1.y, l1.y);
    ((__nv_bfloat162*)g_hn_h)[2*i] = h0;  ((__nv_bfloat162*)g_hn_h)[2*i+1] = h1;
    ((__nv_bfloat162*)g_hn_l)[2*i] = l0;  ((__nv_bfloat162*)g_hn_l)[2*i+1] = l1;
}

// ---------------- edge norm + CSR build ----------------
__global__ void zero_small() {
    int i = blockIdx.x * 256 + threadIdx.x;
    if (i < Nn) { g_deg[i] = 0.f; g_cnt[i] = 0; }
}

__global__ void deg_count_k(const int* __restrict__ row, const int* __restrict__ col,
                            const float* __restrict__ w) {
    int e = blockIdx.x * 256 + threadIdx.x;
    int r = row[e], c = col[e];
    float we = (r == c) ? 0.f : w[e];
    atomicAdd(&g_deg[r], we);
    atomicAdd(&g_cnt[c], 1);
}

__global__ void scan_k() {
    __shared__ int chunk[256];
    int t = threadIdx.x;
    int base = t * 8;
    int s = 0;
    #pragma unroll
    for (int i = 0; i < 8; i++) s += g_cnt[base + i];
    chunk[t] = s;
    __syncthreads();
    for (int o = 1; o < 256; o <<= 1) {
        int v = (t >= o) ? chunk[t - o] : 0;
        __syncthreads();
        chunk[t] += v;
        __syncthreads();
    }
    int run = chunk[t] - s;
    #pragma unroll
    for (int i = 0; i < 8; i++) {
        g_off[base + i] = run;
        g_ptr[base + i] = run;
        run += g_cnt[base + i];
    }
    if (t == 255) g_off[Nn] = run;
}

__global__ void norm_scatter_k(const int* __restrict__ row, const int* __restrict__ col,
                               const float* __restrict__ w) {
    int e = blockIdx.x * 256 + threadIdx.x;
    int r = row[e], c = col[e];
    float we = (r == c) ? 0.f : w[e];
    float dr = g_deg[r], dc = g_deg[c];
    float ir = dr > 0.f ? rsqrtf(fmaxf(dr, 1e-12f)) : 0.f;
    float ic = dc > 0.f ? rsqrtf(fmaxf(dc, 1e-12f)) : 0.f;
    g_norm[e] = -(ir * we * ic);
    int pos = atomicAdd(&g_ptr[c], 1);
    g_csr[pos] = e;
}

// ---------------- sparse propagation (gather, no atomics) ----------------
// first=1: tx1[n] = sum norm*hn[row]          (writes fp32 + hi/lo)
// first=0: tx2[n] = 2*sum norm*tx1[row] - hn  (writes hi/lo only)
__global__ void prop_gather(const int* __restrict__ row, int first) {
    int n = blockIdx.x, b = blockIdx.y;
    int t = threadIdx.x;                    // 64 threads, float4 each
    int s = g_off[n], e = g_off[n + 1];
    const float4* src = (const float4*)(first ? g_hn : g_tx1);
    float4 acc = make_float4(0.f, 0.f, 0.f, 0.f);
    __shared__ int   sr[64];
    __shared__ float sn[64];
    for (int base = s; base < e; base += 64) {
        int cnt = min(64, e - base);
        if (t < cnt) {
            int eid = g_csr[base + t];
            sr[t] = row[eid];
            sn[t] = g_norm[eid];
        }
        __syncthreads();
        for (int j = 0; j < cnt; j++) {
            float nm = sn[j];
            float4 v = __ldg(&src[(size_t)(b * Nn + sr[j]) * 64 + t]);
            acc.x += nm * v.x; acc.y += nm * v.y; acc.z += nm * v.z; acc.w += nm * v.w;
        }
        __syncthreads();
    }
    size_t di = (size_t)(b * Nn + n) * 64 + t;
    float4 o;
    bf16* dh; bf16* dl;
    if (first) {
        o = acc;
        ((float4*)g_tx1)[di] = o;
        dh = g_tx1_h; dl = g_tx1_l;
    } else {
        float4 hv = ((const float4*)g_hn)[di];
        o.x = 2.f * acc.x - hv.x; o.y = 2.f * acc.y - hv.y;
        o.z = 2.f * acc.z - hv.z; o.w = 2.f * acc.w - hv.w;
        dh = g_tx2_h; dl = g_tx2_l;
    }
    __nv_bfloat162 h0, h1, l0, l1;
    split2(o.x, h0.x, l0.x); split2(o.y, h0.y, l0.y);
    split2(o.z, h1.x, l1.x); split2(o.w, h1.y, l1.y);
    ((__nv_bfloat162*)dh)[2*di] = h0;  ((__nv_bfloat162*)dh)[2*di+1] = h1;
    ((__nv_bfloat162*)dl)[2*di] = l0;  ((__nv_bfloat162*)dl)[2*di+1] = l1;
}

// ---------------- tensor-core GEMM (bf16 split, 3 passes) ----------------
// C[16384,256]: MODE 0: h += (sum_seg A_seg@Wch_seg) + bias
//               MODE 1: h += gelu(hn@Wmlp + bias)
// A@W = Ah@Wh + Al@Wh + Ah@Wl  (Al@Wl dropped, ~2^-16 relative)

#define GBM 128
#define GBN 64
#define GBK 64
#define APAD 72   // 64 + 8 bf16 (keeps 16B alignment)

__device__ __forceinline__ uint32_t smem_u32(const void* p) {
    return (uint32_t)__cvta_generic_to_shared(p);
}
__device__ __forceinline__ void ldm_x4(uint32_t* r, uint32_t a) {
    asm volatile("ldmatrix.sync.aligned.m8n8.x4.shared.b16 {%0,%1,%2,%3}, [%4];"
                 : "=r"(r[0]), "=r"(r[1]), "=r"(r[2]), "=r"(r[3]) : "r"(a));
}
__device__ __forceinline__ void ldm_x4_t(uint32_t* r, uint32_t a) {
    asm volatile("ldmatrix.sync.aligned.m8n8.x4.trans.shared.b16 {%0,%1,%2,%3}, [%4];"
                 : "=r"(r[0]), "=r"(r[1]), "=r"(r[2]), "=r"(r[3]) : "r"(a));
}
__device__ __forceinline__ void mma16816(float* d, const uint32_t* a, const uint32_t* b) {
    asm volatile("mma.sync.aligned.m16n8k16.row.col.f32.bf16.bf16.f32 "
                 "{%0,%1,%2,%3},{%4,%5,%6,%7},{%8,%9},{%0,%1,%2,%3};"
                 : "+f"(d[0]), "+f"(d[1]), "+f"(d[2]), "+f"(d[3])
                 : "r"(a[0]), "r"(a[1]), "r"(a[2]), "r"(a[3]), "r"(b[0]), "r"(b[1]));
}

__device__ __forceinline__ float gelu_exact(float v) {
    return 0.5f * v * (1.f + erff(v * 0.70710678118654752f));
}

// resolve per-stage sources (plain function, no lambda)
template<int MODE>
__device__ __forceinline__ void stage_src(int s, int l, const bf16*& Ap, const bf16*& Wp, int& kc) {
    int seg, pass;
    if (MODE == 0) { seg = s / 12; int r = s % 12; pass = r >> 2; kc = r & 3; }
    else           { seg = 0;      int r = s;      pass = r >> 2; kc = r & 3; }
    if (MODE == 0) {
        const bf16* Aarr[6] = { g_hn_h, g_hn_l, g_tx1_h, g_tx1_l, g_tx2_h, g_tx2_l };
        Ap = Aarr[seg * 2 + (pass == 1)];
        Wp = ((pass == 2) ? g_wch_l : g_wch_h) + (size_t)(l * 3 + seg) * Cc * Cc;
    } else {
        Ap = (pass == 1) ? g_hn_l : g_hn_h;
        Wp = ((pass == 2) ? g_wml_l : g_wml_h) + (size_t)l * Cc * Cc;
    }
}

template<int MODE>
__global__ __launch_bounds__(256, 1) void tc_gemm(int l, const float* __restrict__ bias) {
    extern __shared__ __align__(16) char smem_raw[];
    bf16 (*As)[GBM][APAD] = (bf16 (*)[GBM][APAD])smem_raw;                       // [2][128][72]
    bf16 (*Bs)[GBK][APAD] = (bf16 (*)[GBK][APAD])(smem_raw + 2*GBM*APAD*2);      // [2][64][72]

    const int m0 = blockIdx.x * GBM, n0 = blockIdx.y * GBN;
    const int tid = threadIdx.x;
    const int wid = tid >> 5, lane = tid & 31;
    const int wm = wid >> 1, wn = wid & 1;           // warp tile: 32x32 at (wm*32, wn*32)
    const int lrow = lane & 15, lsel = lane >> 4;

    const int NST = (MODE == 0) ? 36 : 12;

    // loader index precompute: A: 4 chunks of 16B, B: 2 chunks
    const int ar_[4] = { (tid + 0) >> 3, (tid + 256) >> 3, (tid + 512) >> 3, (tid + 768) >> 3 };
    const int ac_ = (tid & 7) * 8;
    const int br_[2] = { (tid + 0) >> 3, (tid + 256) >> 3 };

    float acc[2][4][4] = {};

    uint4 pa[4], pb[2];
    {   // prologue: stage 0 -> regs -> smem[0]
        const bf16 *Ap, *Wp; int kc;
        stage_src<MODE>(0, l, Ap, Wp, kc);
        #pragma unroll
        for (int i = 0; i < 4; i++)
            pa[i] = *(const uint4*)(Ap + (size_t)(m0 + ar_[i]) * Cc + kc * GBK + ac_);
        #pragma unroll
        for (int i = 0; i < 2; i++)
            pb[i] = *(const uint4*)(Wp + (size_t)(kc * GBK + br_[i]) * Cc + n0 + ac_);
        #pragma unroll
        for (int i = 0; i < 4; i++) *(uint4*)&As[0][ar_[i]][ac_] = pa[i];
        #pragma unroll
        for (int i = 0; i < 2; i++) *(uint4*)&Bs[0][br_[i]][ac_] = pb[i];
    }
    __syncthreads();

    for (int s = 0; s < NST; s++) {
        int cur = s & 1;
        if (s + 1 < NST) {
            const bf16 *Ap, *Wp; int kc;
            stage_src<MODE>(s + 1, l, Ap, Wp, kc);
            #pragma unroll
            for (int i = 0; i < 4; i++)
                pa[i] = *(const uint4*)(Ap + (size_t)(m0 + ar_[i]) * Cc + kc * GBK + ac_);
            #pragma unroll
            for (int i = 0; i < 2; i++)
                pb[i] = *(const uint4*)(Wp + (size_t)(kc * GBK + br_[i]) * Cc + n0 + ac_);
        }
        #pragma unroll
        for (int ks = 0; ks < 4; ks++) {
            uint32_t af[2][4], bfr[2][4];
            #pragma unroll
            for (int mt = 0; mt < 2; mt++)
                ldm_x4(af[mt], smem_u32(&As[cur][wm * 32 + mt * 16 + lrow][ks * 16 + lsel * 8]));
            #pragma unroll
            for (int nt2 = 0; nt2 < 2; nt2++)
                ldm_x4_t(bfr[nt2], smem_u32(&Bs[cur][ks * 16 + lrow][wn * 32 + nt2 * 16 + lsel * 8]));
            #pragma unroll
            for (int mt = 0; mt < 2; mt++)
                #pragma unroll
                for (int nt = 0; nt < 4; nt++)
                    mma16816(acc[mt][nt], af[mt], &bfr[nt >> 1][(nt & 1) * 2]);
        }
        if (s + 1 < NST) {
            int nxt = (s + 1) & 1;
            #pragma unroll
            for (int i = 0; i < 4; i++) *(uint4*)&As[nxt][ar_[i]][ac_] = pa[i];
            #pragma unroll
            for (int i = 0; i < 2; i++) *(uint4*)&Bs[nxt][br_[i]][ac_] = pb[i];
            __syncthreads();
        }
    }

    // epilogue: C += acc (+bias / gelu), RMW on g_h fp32
    const int grp = lane >> 2, qc = lane & 3;
    #pragma unroll
    for (int mt = 0; mt < 2; mt++) {
        #pragma unroll
        for (int nt = 0; nt < 4; nt++) {
            int r0 = m0 + wm * 32 + mt * 16 + grp;
            int c0 = n0 + wn * 32 + nt * 8 + qc * 2;
            float b0 = bias[c0], b1 = bias[c0 + 1];
            #pragma unroll
            for (int hh = 0; hh < 2; hh++) {
                int r = r0 + hh * 8;
                float2* hp = (float2*)(g_h + (size_t)r * Cc + c0);
                float2 hv = *hp;
                float v0 = acc[mt][nt][hh * 2 + 0] + b0;
                float v1 = acc[mt][nt][hh * 2 + 1] + b1;
                if (MODE == 0) { hv.x += v0; hv.y += v1; }
                else           { hv.x += gelu_exact(v0); hv.y += gelu_exact(v1); }
                *hp = hv;
            }
        }
    }
}

// ---------------- final mean over nodes ----------------
__global__ void zero_out(float* __restrict__ out) {
    int i = blockIdx.x * 256 + threadIdx.x;
    if (i < Bq * Cc) out[i] = 0.f;
}

__global__ void mean_k(float* __restrict__ out) {
    int b = blockIdx.x, chunk = blockIdx.y;
    int c = threadIdx.x;
    float s = 0.f;
    int nb = chunk * 128;
    const float* base = g_h + (size_t)b * Nn * Cc + c;
    for (int n = nb; n < nb + 128; n++) s += base[(size_t)n * Cc];
    atomicAdd(&out[b * Cc + c], s * (1.f / (float)Nn));
}

// ---------------- launch ----------------
extern "C" void kernel_launch(void* const* d_in, const int* in_sizes, int n_in,
                              void* d_out, int out_size) {
    const float* nf = (const float*)d_in[0];   // node_feature [8,2048,256]
    const float* ew = (const float*)d_in[1];   // edge_weight  [3,32768]
    const float* cw = (const float*)d_in[2];   // cheb_w [3,3,256,256]
    const float* cb = (const float*)d_in[3];   // cheb_b [3,256]
    const float* mw = (const float*)d_in[4];   // mlp_w  [3,256,256]
    const float* mb = (const float*)d_in[5];   // mlp_b  [3,256]
    const int*   ei = (const int*)d_in[6];     // edge_index [3,2,32768]
    float* out = (float*)d_out;                // [8,256]

    const int SMEM = 2 * GBM * APAD * 2 + 2 * GBK * APAD * 2;   // 55296 B
    cudaFuncSetAttribute(tc_gemm<0>, cudaFuncAttributeMaxDynamicSharedMemorySize, SMEM);
    cudaFuncSetAttribute(tc_gemm<1>, cudaFuncAttributeMaxDynamicSharedMemorySize, SMEM);

    copy_init<<<TOT / 1024, 256>>>(nf);
    split_w<<<(3 * 3 * Cc * Cc + 255) / 256, 256>>>(cw, mw);

    for (int l = 0; l < 3; l++) {
        const int* row = ei + l * 2 * Ee;
        const int* col = row + Ee;
        const float* w = ew + l * Ee;

        // LN -> hn (+ bf16 split)
        reduce_partial<<<RB, 256>>>();
        reduce_final<<<1, RB>>>();
        normalize_k<<<TOT / 1024, 256>>>();

        // edge normalization + CSR (by col)
        zero_small<<<8, 256>>>();
        deg_count_k<<<Ee / 256, 256>>>(row, col, w);
        scan_k<<<1, 256>>>();
        norm_scatter_k<<<Ee / 256, 256>>>(row, col, w);

        // Chebyshev props (gather)
        prop_gather<<<dim3(Nn, Bq), 64>>>(row, 1);   // tx1
        prop_gather<<<dim3(Nn, Bq), 64>>>(row, 0);   // tx2

        // tensor-core Cheb GEMM + bias + residual
        tc_gemm<0><<<dim3(Mr / GBM, Cc / GBN), 256, SMEM>>>(l, cb + l * Cc);

        // LN -> hn
        reduce_partial<<<RB, 256>>>();
        reduce_final<<<1, RB>>>();
        normalize_k<<<TOT / 1024, 256>>>();

        // tensor-core MLP + GELU + residual
        tc_gemm<1><<<dim3(Mr / GBM, Cc / GBN), 256, SMEM>>>(l, mb + l * Cc);
    }
    zero_out<<<8, 256>>>(out);
    mean_k<<<dim3(Bq, 16), 256>>>(out);
}

// round 8
// speedup vs baseline: 1.6414x; 1.0142x over previous
#include <cuda_runtime.h>
#include <cuda_bf16.h>
#include <math.h>
#include <stdint.h>

#define Bq 8
#define Nn 2048
#define Cc 256
#define Ee 32768
#define TOT (Bq*Nn*Cc)      // 4194304
#define Mr  (Bq*Nn)         // 16384
#define RB  256

typedef __nv_bfloat16 bf16;

// Persistent scratch (device globals; no allocations allowed)
__device__ __align__(16) float g_h[TOT];
__device__ __align__(16) float g_hn[TOT];
__device__ __align__(16) float g_tx1[TOT];
__device__ __align__(16) bf16  g_hn_h[TOT],  g_hn_l[TOT];
__device__ __align__(16) bf16  g_tx1_h[TOT], g_tx1_l[TOT];
__device__ __align__(16) bf16  g_tx2_h[TOT], g_tx2_l[TOT];
__device__ __align__(16) bf16  g_wch_h[3*3*Cc*Cc], g_wch_l[3*3*Cc*Cc];
__device__ __align__(16) bf16  g_wml_h[3*Cc*Cc],   g_wml_l[3*Cc*Cc];
__device__ float g_deg[3][Nn];
__device__ float g_norm[3][Ee];
__device__ float g_psum[RB];
__device__ float g_psq[RB];
// CSR by destination (col), per layer
__device__ int g_cnt[3][Nn];
__device__ int g_off[3][Nn + 1];
__device__ int g_ptr[3][Nn];
__device__ int g_csr[3][Ee];

__device__ __forceinline__ void split2(float x, bf16& h, bf16& l) {
    h = __float2bfloat16(x);
    l = __float2bfloat16(x - __bfloat162float(h));
}

// ---------------- init ----------------
__global__ void copy_init(const float* __restrict__ x) {
    int i = blockIdx.x * 256 + threadIdx.x;          // over TOT/4
    ((float4*)g_h)[i] = ((const float4*)x)[i];
}

// split weights once per launch
__global__ void split_w(const float* __restrict__ cw, const float* __restrict__ mw) {
    int i = blockIdx.x * 256 + threadIdx.x;
    int NC = 3 * 3 * Cc * Cc;
    if (i < NC) split2(cw[i], g_wch_h[i], g_wch_l[i]);
    if (i < 3 * Cc * Cc) split2(mw[i], g_wml_h[i], g_wml_l[i]);
}

// ---------------- CSR build (all 3 layers, once per launch) ----------------
__global__ void zero_small3() {
    int i = blockIdx.x * 256 + threadIdx.x;          // over 3*Nn
    if (i < 3 * Nn) { ((float*)g_deg)[i] = 0.f; ((int*)g_cnt)[i] = 0; }
}

__global__ void deg_count3(const int* __restrict__ ei, const float* __restrict__ ew) {
    int l = blockIdx.y;
    int e = blockIdx.x * 256 + threadIdx.x;
    const int* row = ei + l * 2 * Ee;
    const int* col = row + Ee;
    int r = row[e], c = col[e];
    float we = (r == c) ? 0.f : ew[l * Ee + e];
    atomicAdd(&g_deg[l][r], we);
    atomicAdd(&g_cnt[l][c], 1);
}

__global__ void scan3() {
    int l = blockIdx.x;
    __shared__ int chunk[256];
    int t = threadIdx.x;
    int base = t * 8;
    int s = 0;
    #pragma unroll
    for (int i = 0; i < 8; i++) s += g_cnt[l][base + i];
    chunk[t] = s;
    __syncthreads();
    for (int o = 1; o < 256; o <<= 1) {
        int v = (t >= o) ? chunk[t - o] : 0;
        __syncthreads();
        chunk[t] += v;
        __syncthreads();
    }
    int run = chunk[t] - s;
    #pragma unroll
    for (int i = 0; i < 8; i++) {
        g_off[l][base + i] = run;
        g_ptr[l][base + i] = run;
        run += g_cnt[l][base + i];
    }
    if (t == 255) g_off[l][Nn] = run;
}

__global__ void norm_scatter3(const int* __restrict__ ei, const float* __restrict__ ew) {
    int l = blockIdx.y;
    int e = blockIdx.x * 256 + threadIdx.x;
    const int* row = ei + l * 2 * Ee;
    const int* col = row + Ee;
    int r = row[e], c = col[e];
    float we = (r == c) ? 0.f : ew[l * Ee + e];
    float dr = g_deg[l][r], dc = g_deg[l][c];
    float ir = dr > 0.f ? rsqrtf(fmaxf(dr, 1e-12f)) : 0.f;
    float ic = dc > 0.f ? rsqrtf(fmaxf(dc, 1e-12f)) : 0.f;
    g_norm[l][e] = -(ir * we * ic);
    int pos = atomicAdd(&g_ptr[l][c], 1);
    g_csr[l][pos] = e;
}

// ---------------- global LayerNorm ----------------
__global__ void reduce_partial() {
    int tid = blockIdx.x * blockDim.x + threadIdx.x;
    int stride = gridDim.x * blockDim.x;
    const float4* x4 = (const float4*)g_h;
    float s = 0.f, q = 0.f;
    for (int i = tid; i < TOT / 4; i += stride) {
        float4 v = x4[i];
        s += (v.x + v.y) + (v.z + v.w);
        q += v.x * v.x + v.y * v.y + v.z * v.z + v.w * v.w;
    }
    __shared__ float ss[256], sq[256];
    ss[threadIdx.x] = s; sq[threadIdx.x] = q;
    __syncthreads();
    for (int o = 128; o > 0; o >>= 1) {
        if (threadIdx.x < o) { ss[threadIdx.x] += ss[threadIdx.x + o]; sq[threadIdx.x] += sq[threadIdx.x + o]; }
        __syncthreads();
    }
    if (threadIdx.x == 0) { g_psum[blockIdx.x] = ss[0]; g_psq[blockIdx.x] = sq[0]; }
}

// each block reduces the RB partials itself, then normalizes its 1024 elements
// hn = (h-m)*r ; also emit bf16 hi/lo split
__global__ void normalize_k() {
    __shared__ float ss[RB], sq[RB];
    __shared__ float s_m, s_r;
    int t = threadIdx.x;
    ss[t] = g_psum[t]; sq[t] = g_psq[t];
    __syncthreads();
    #pragma unroll
    for (int o = RB / 2; o > 0; o >>= 1) {
        if (t < o) { ss[t] += ss[t + o]; sq[t] += sq[t + o]; }
        __syncthreads();
    }
    if (t == 0) {
        float mean = ss[0] / (float)TOT;
        float var  = sq[0] / (float)TOT - mean * mean;
        s_m = mean;
        s_r = rsqrtf(var + 1e-5f);
    }
    __syncthreads();
    float m = s_m, r = s_r;
    int i = blockIdx.x * 256 + t;                    // over TOT/4
    float4 v = ((const float4*)g_h)[i];
    float4 o;
    o.x = (v.x - m) * r; o.y = (v.y - m) * r; o.z = (v.z - m) * r; o.w = (v.w - m) * r;
    ((float4*)g_hn)[i] = o;
    __nv_bfloat162 h0, h1, l0, l1;
    split2(o.x, h0.x, l0.x); split2(o.y, h0.y, l0.y);
    split2(o.z, h1.x, l1.x); split2(o.w, h1.y, l1.y);
    ((__nv_bfloat162*)g_hn_h)[2*i] = h0;  ((__nv_bfloat162*)g_hn_h)[2*i+1] = h1;
    ((__nv_bfloat162*)g_hn_l)[2*i] = l0;  ((__nv_bfloat162*)g_hn_l)[2*i+1] = l1;
}

// ---------------- sparse propagation (gather, no atomics, 4x unroll) ----------------
// first=1: tx1[n] = sum norm*hn[row]          (writes fp32 + hi/lo)
// first=0: tx2[n] = 2*sum norm*tx1[row] - hn  (writes hi/lo only)
__global__ void prop_gather(const int* __restrict__ row, int l, int first) {
    int n = blockIdx.x, b = blockIdx.y;
    int t = threadIdx.x;                    // 64 threads, float4 each
    int s = g_off[l][n], e = g_off[l][n + 1];
    const float4* src = (const float4*)(first ? g_hn : g_tx1);
    const float4* srcb = src + (size_t)b * Nn * 64;
    float4 acc = make_float4(0.f, 0.f, 0.f, 0.f);
    __shared__ int   sr[64];
    __shared__ float sn[64];
    for (int base = s; base < e; base += 64) {
        int cnt = min(64, e - base);
        if (t < cnt) {
            int eid = g_csr[l][base + t];
            sr[t] = row[eid];
            sn[t] = g_norm[l][eid];
        }
        __syncthreads();
        int j = 0;
        for (; j + 4 <= cnt; j += 4) {
            float n0 = sn[j], n1 = sn[j+1], n2 = sn[j+2], n3 = sn[j+3];
            float4 v0 = __ldg(&srcb[(size_t)sr[j]   * 64 + t]);
            float4 v1 = __ldg(&srcb[(size_t)sr[j+1] * 64 + t]);
            float4 v2 = __ldg(&srcb[(size_t)sr[j+2] * 64 + t]);
            float4 v3 = __ldg(&srcb[(size_t)sr[j+3] * 64 + t]);
            acc.x += n0*v0.x + n1*v1.x + n2*v2.x + n3*v3.x;
            acc.y += n0*v0.y + n1*v1.y + n2*v2.y + n3*v3.y;
            acc.z += n0*v0.z + n1*v1.z + n2*v2.z + n3*v3.z;
            acc.w += n0*v0.w + n1*v1.w + n2*v2.w + n3*v3.w;
        }
        for (; j < cnt; j++) {
            float nm = sn[j];
            float4 v = __ldg(&srcb[(size_t)sr[j] * 64 + t]);
            acc.x += nm * v.x; acc.y += nm * v.y; acc.z += nm * v.z; acc.w += nm * v.w;
        }
        __syncthreads();
    }
    size_t di = (size_t)(b * Nn + n) * 64 + t;
    float4 o;
    bf16* dh; bf16* dl;
    if (first) {
        o = acc;
        ((float4*)g_tx1)[di] = o;
        dh = g_tx1_h; dl = g_tx1_l;
    } else {
        float4 hv = ((const float4*)g_hn)[di];
        o.x = 2.f * acc.x - hv.x; o.y = 2.f * acc.y - hv.y;
        o.z = 2.f * acc.z - hv.z; o.w = 2.f * acc.w - hv.w;
        dh = g_tx2_h; dl = g_tx2_l;
    }
    __nv_bfloat162 h0, h1, l0, l1;
    split2(o.x, h0.x, l0.x); split2(o.y, h0.y, l0.y);
    split2(o.z, h1.x, l1.x); split2(o.w, h1.y, l1.y);
    ((__nv_bfloat162*)dh)[2*di] = h0;  ((__nv_bfloat162*)dh)[2*di+1] = h1;
    ((__nv_bfloat162*)dl)[2*di] = l0;  ((__nv_bfloat162*)dl)[2*di+1] = l1;
}

// ---------------- tensor-core GEMM (bf16 split, 3 passes) ----------------
#define GBM 128
#define GBN 64
#define GBK 64
#define APAD 72   // 64 + 8 bf16 (keeps 16B alignment)

__device__ __forceinline__ uint32_t smem_u32(const void* p) {
    return (uint32_t)__cvta_generic_to_shared(p);
}
__device__ __forceinline__ void ldm_x4(uint32_t* r, uint32_t a) {
    asm volatile("ldmatrix.sync.aligned.m8n8.x4.shared.b16 {%0,%1,%2,%3}, [%4];"
                 : "=r"(r[0]), "=r"(r[1]), "=r"(r[2]), "=r"(r[3]) : "r"(a));
}
__device__ __forceinline__ void ldm_x4_t(uint32_t* r, uint32_t a) {
    asm volatile("ldmatrix.sync.aligned.m8n8.x4.trans.shared.b16 {%0,%1,%2,%3}, [%4];"
                 : "=r"(r[0]), "=r"(r[1]), "=r"(r[2]), "=r"(r[3]) : "r"(a));
}
__device__ __forceinline__ void mma16816(float* d, const uint32_t* a, const uint32_t* b) {
    asm volatile("mma.sync.aligned.m16n8k16.row.col.f32.bf16.bf16.f32 "
                 "{%0,%1,%2,%3},{%4,%5,%6,%7},{%8,%9},{%0,%1,%2,%3};"
                 : "+f"(d[0]), "+f"(d[1]), "+f"(d[2]), "+f"(d[3])
                 : "r"(a[0]), "r"(a[1]), "r"(a[2]), "r"(a[3]), "r"(b[0]), "r"(b[1]));
}

__device__ __forceinline__ float gelu_exact(float v) {
    return 0.5f * v * (1.f + erff(v * 0.70710678118654752f));
}

template<int MODE>
__device__ __forceinline__ void stage_src(int s, int l, const bf16*& Ap, const bf16*& Wp, int& kc) {
    int seg, pass;
    if (MODE == 0) { seg = s / 12; int r = s % 12; pass = r >> 2; kc = r & 3; }
    else           { seg = 0;      int r = s;      pass = r >> 2; kc = r & 3; }
    if (MODE == 0) {
        const bf16* Aarr[6] = { g_hn_h, g_hn_l, g_tx1_h, g_tx1_l, g_tx2_h, g_tx2_l };
        Ap = Aarr[seg * 2 + (pass == 1)];
        Wp = ((pass == 2) ? g_wch_l : g_wch_h) + (size_t)(l * 3 + seg) * Cc * Cc;
    } else {
        Ap = (pass == 1) ? g_hn_l : g_hn_h;
        Wp = ((pass == 2) ? g_wml_l : g_wml_h) + (size_t)l * Cc * Cc;
    }
}

template<int MODE>
__global__ __launch_bounds__(256, 1) void tc_gemm(int l, const float* __restrict__ bias) {
    extern __shared__ __align__(16) char smem_raw[];
    bf16 (*As)[GBM][APAD] = (bf16 (*)[GBM][APAD])smem_raw;                       // [2][128][72]
    bf16 (*Bs)[GBK][APAD] = (bf16 (*)[GBK][APAD])(smem_raw + 2*GBM*APAD*2);      // [2][64][72]

    const int m0 = blockIdx.x * GBM, n0 = blockIdx.y * GBN;
    const int tid = threadIdx.x;
    const int wid = tid >> 5, lane = tid & 31;
    const int wm = wid >> 1, wn = wid & 1;           // warp tile: 32x32
    const int lrow = lane & 15, lsel = lane >> 4;

    const int NST = (MODE == 0) ? 36 : 12;

    const int ar_[4] = { (tid + 0) >> 3, (tid + 256) >> 3, (tid + 512) >> 3, (tid + 768) >> 3 };
    const int ac_ = (tid & 7) * 8;
    const int br_[2] = { (tid + 0) >> 3, (tid + 256) >> 3 };

    float acc[2][4][4] = {};

    uint4 pa[4], pb[2];
    {
        const bf16 *Ap, *Wp; int kc;
        stage_src<MODE>(0, l, Ap, Wp, kc);
        #pragma unroll
        for (int i = 0; i < 4; i++)
            pa[i] = *(const uint4*)(Ap + (size_t)(m0 + ar_[i]) * Cc + kc * GBK + ac_);
        #pragma unroll
        for (int i = 0; i < 2; i++)
            pb[i] = *(const uint4*)(Wp + (size_t)(kc * GBK + br_[i]) * Cc + n0 + ac_);
        #pragma unroll
        for (int i = 0; i < 4; i++) *(uint4*)&As[0][ar_[i]][ac_] = pa[i];
        #pragma unroll
        for (int i = 0; i < 2; i++) *(uint4*)&Bs[0][br_[i]][ac_] = pb[i];
    }
    __syncthreads();

    for (int s = 0; s < NST; s++) {
        int cur = s & 1;
        if (s + 1 < NST) {
            const bf16 *Ap, *Wp; int kc;
            stage_src<MODE>(s + 1, l, Ap, Wp, kc);
            #pragma unroll
            for (int i = 0; i < 4; i++)
                pa[i] = *(const uint4*)(Ap + (size_t)(m0 + ar_[i]) * Cc + kc * GBK + ac_);
            #pragma unroll
            for (int i = 0; i < 2; i++)
                pb[i] = *(const uint4*)(Wp + (size_t)(kc * GBK + br_[i]) * Cc + n0 + ac_);
        }
        #pragma unroll
        for (int ks = 0; ks < 4; ks++) {
            uint32_t af[2][4], bfr[2][4];
            #pragma unroll
            for (int mt = 0; mt < 2; mt++)
                ldm_x4(af[mt], smem_u32(&As[cur][wm * 32 + mt * 16 + lrow][ks * 16 + lsel * 8]));
            #pragma unroll
            for (int nt2 = 0; nt2 < 2; nt2++)
                ldm_x4_t(bfr[nt2], smem_u32(&Bs[cur][ks * 16 + lrow][wn * 32 + nt2 * 16 + lsel * 8]));
            #pragma unroll
            for (int mt = 0; mt < 2; mt++)
                #pragma unroll
                for (int nt = 0; nt < 4; nt++)
                    mma16816(acc[mt][nt], af[mt], &bfr[nt >> 1][(nt & 1) * 2]);
        }
        if (s + 1 < NST) {
            int nxt = (s + 1) & 1;
            #pragma unroll
            for (int i = 0; i < 4; i++) *(uint4*)&As[nxt][ar_[i]][ac_] = pa[i];
            #pragma unroll
            for (int i = 0; i < 2; i++) *(uint4*)&Bs[nxt][br_[i]][ac_] = pb[i];
            __syncthreads();
        }
    }

    const int grp = lane >> 2, qc = lane & 3;
    #pragma unroll
    for (int mt = 0; mt < 2; mt++) {
        #pragma unroll
        for (int nt = 0; nt < 4; nt++) {
            int r0 = m0 + wm * 32 + mt * 16 + grp;
            int c0 = n0 + wn * 32 + nt * 8 + qc * 2;
            float b0 = bias[c0], b1 = bias[c0 + 1];
            #pragma unroll
            for (int hh = 0; hh < 2; hh++) {
                int r = r0 + hh * 8;
                float2* hp = (float2*)(g_h + (size_t)r * Cc + c0);
                float2 hv = *hp;
                float v0 = acc[mt][nt][hh * 2 + 0] + b0;
                float v1 = acc[mt][nt][hh * 2 + 1] + b1;
                if (MODE == 0) { hv.x += v0; hv.y += v1; }
                else           { hv.x += gelu_exact(v0); hv.y += gelu_exact(v1); }
                *hp = hv;
            }
        }
    }
}

// ---------------- final mean over nodes ----------------
__global__ void zero_out(float* __restrict__ out) {
    int i = blockIdx.x * 256 + threadIdx.x;
    if (i < Bq * Cc) out[i] = 0.f;
}

__global__ void mean_k(float* __restrict__ out) {
    int b = blockIdx.x, chunk = blockIdx.y;
    int c = threadIdx.x;
    float s = 0.f;
    int nb = chunk * 128;
    const float* base = g_h + (size_t)b * Nn * Cc + c;
    for (int n = nb; n < nb + 128; n++) s += base[(size_t)n * Cc];
    atomicAdd(&out[b * Cc + c], s * (1.f / (float)Nn));
}

// ---------------- launch ----------------
extern "C" void kernel_launch(void* const* d_in, const int* in_sizes, int n_in,
                              void* d_out, int out_size) {
    const float* nf = (const float*)d_in[0];   // node_feature [8,2048,256]
    const float* ew = (const float*)d_in[1];   // edge_weight  [3,32768]
    const float* cw = (const float*)d_in[2];   // cheb_w [3,3,256,256]
    const float* cb = (const float*)d_in[3];   // cheb_b [3,256]
    const float* mw = (const float*)d_in[4];   // mlp_w  [3,256,256]
    const float* mb = (const float*)d_in[5];   // mlp_b  [3,256]
    const int*   ei = (const int*)d_in[6];     // edge_index [3,2,32768]
    float* out = (float*)d_out;                // [8,256]

    const int SMEM = 2 * GBM * APAD * 2 + 2 * GBK * APAD * 2;   // 55296 B
    cudaFuncSetAttribute(tc_gemm<0>, cudaFuncAttributeMaxDynamicSharedMemorySize, SMEM);
    cudaFuncSetAttribute(tc_gemm<1>, cudaFuncAttributeMaxDynamicSharedMemorySize, SMEM);

    copy_init<<<TOT / 1024, 256>>>(nf);
    split_w<<<(3 * 3 * Cc * Cc + 255) / 256, 256>>>(cw, mw);

    // CSR + edge norm for all 3 layers (constant across layers)
    zero_small3<<<(3 * Nn + 255) / 256, 256>>>();
    deg_count3<<<dim3(Ee / 256, 3), 256>>>(ei, ew);
    scan3<<<3, 256>>>();
    norm_scatter3<<<dim3(Ee / 256, 3), 256>>>(ei, ew);

    for (int l = 0; l < 3; l++) {
        const int* row = ei + l * 2 * Ee;

        // LN -> hn (+ bf16 split); stats folded into normalize
        reduce_partial<<<RB, 256>>>();
        normalize_k<<<TOT / 1024, 256>>>();

        // Chebyshev props (gather)
        prop_gather<<<dim3(Nn, Bq), 64>>>(row, l, 1);   // tx1
        prop_gather<<<dim3(Nn, Bq), 64>>>(row, l, 0);   // tx2

        // tensor-core Cheb GEMM + bias + residual
        tc_gemm<0><<<dim3(Mr / GBM, Cc / GBN), 256, SMEM>>>(l, cb + l * Cc);

        // LN -> hn
        reduce_partial<<<RB, 256>>>();
        normalize_k<<<TOT / 1024, 256>>>();

        // tensor-core MLP + GELU + residual
        tc_gemm<1><<<dim3(Mr / GBM, Cc / GBN), 256, SMEM>>>(l, mb + l * Cc);
    }
    zero_out<<<8, 256>>>(out);
    mean_k<<<dim3(Bq, 16), 256>>>(out);
}

// round 9
// speedup vs baseline: 1.9042x; 1.1601x over previous
#include <cuda_runtime.h>
#include <cuda_bf16.h>
#include <math.h>
#include <stdint.h>

#define Bq 8
#define Nn 2048
#define Cc 256
#define Ee 32768
#define TOT (Bq*Nn*Cc)      // 4194304
#define Mr  (Bq*Nn)         // 16384

typedef __nv_bfloat16 bf16;

// Persistent scratch (device globals; no allocations allowed)
__device__ __align__(16) float g_h[TOT];
__device__ __align__(16) float g_tx1[TOT];
__device__ __align__(16) bf16  g_hn_h[TOT],  g_hn_l[TOT];
__device__ __align__(16) bf16  g_tx1_h[TOT], g_tx1_l[TOT];
__device__ __align__(16) bf16  g_tx2_h[TOT], g_tx2_l[TOT];
__device__ __align__(16) bf16  g_wch_h[3*3*Cc*Cc], g_wch_l[3*3*Cc*Cc];
__device__ __align__(16) bf16  g_wml_h[3*Cc*Cc],   g_wml_l[3*Cc*Cc];
__device__ float g_deg[3][Nn];
__device__ float g_norm[3][Ee];
__device__ float g_snorm[3][Nn];   // per-node sum of norm (incoming)
__device__ float g_sred[14];       // 7 slots x {sum, sumsq}
// CSR by destination (col), per layer
__device__ int g_cnt[3][Nn];
__device__ int g_off[3][Nn + 1];
__device__ int g_ptr[3][Nn];
__device__ int g_csr[3][Ee];

__device__ __forceinline__ void split2(float x, bf16& h, bf16& l) {
    h = __float2bfloat16(x);
    l = __float2bfloat16(x - __bfloat162float(h));
}

// block-reduce (ls,lq) over 256 threads and atomically add into slot
__device__ __forceinline__ void stats_commit(float ls, float lq, int slot) {
    int lane = threadIdx.x & 31, wid = threadIdx.x >> 5;
    #pragma unroll
    for (int o = 16; o > 0; o >>= 1) {
        ls += __shfl_xor_sync(0xffffffffu, ls, o);
        lq += __shfl_xor_sync(0xffffffffu, lq, o);
    }
    __shared__ float ws[8], wq[8];
    if (lane == 0) { ws[wid] = ls; wq[wid] = lq; }
    __syncthreads();
    if (threadIdx.x == 0) {
        float s = 0.f, q = 0.f;
        #pragma unroll
        for (int i = 0; i < 8; i++) { s += ws[i]; q += wq[i]; }
        atomicAdd(&g_sred[slot * 2 + 0], s);
        atomicAdd(&g_sred[slot * 2 + 1], q);
    }
}

__device__ __forceinline__ void stats_fetch(int slot, float& m, float& r) {
    float s = g_sred[slot * 2 + 0], q = g_sred[slot * 2 + 1];
    m = s / (float)TOT;
    float var = q / (float)TOT - m * m;
    r = rsqrtf(var + 1e-5f);
}

// ---------------- init ----------------
__global__ void zero_sred() {
    if (threadIdx.x < 14) g_sred[threadIdx.x] = 0.f;
}

__global__ void copy_init(const float* __restrict__ x) {
    int i = blockIdx.x * 256 + threadIdx.x;          // over TOT/4
    float4 v = ((const float4*)x)[i];
    ((float4*)g_h)[i] = v;
    float ls = (v.x + v.y) + (v.z + v.w);
    float lq = v.x*v.x + v.y*v.y + v.z*v.z + v.w*v.w;
    stats_commit(ls, lq, 0);
}

// split weights once per launch
__global__ void split_w(const float* __restrict__ cw, const float* __restrict__ mw) {
    int i = blockIdx.x * 256 + threadIdx.x;
    int NC = 3 * 3 * Cc * Cc;
    if (i < NC) split2(cw[i], g_wch_h[i], g_wch_l[i]);
    if (i < 3 * Cc * Cc) split2(mw[i], g_wml_h[i], g_wml_l[i]);
}

// ---------------- CSR build (all 3 layers, once per launch) ----------------
__global__ void zero_small3() {
    int i = blockIdx.x * 256 + threadIdx.x;          // over 3*Nn
    if (i < 3 * Nn) {
        ((float*)g_deg)[i] = 0.f;
        ((float*)g_snorm)[i] = 0.f;
        ((int*)g_cnt)[i] = 0;
    }
}

__global__ void deg_count3(const int* __restrict__ ei, const float* __restrict__ ew) {
    int l = blockIdx.y;
    int e = blockIdx.x * 256 + threadIdx.x;
    const int* row = ei + l * 2 * Ee;
    const int* col = row + Ee;
    int r = row[e], c = col[e];
    float we = (r == c) ? 0.f : ew[l * Ee + e];
    atomicAdd(&g_deg[l][r], we);
    atomicAdd(&g_cnt[l][c], 1);
}

__global__ void scan3() {
    int l = blockIdx.x;
    __shared__ int chunk[256];
    int t = threadIdx.x;
    int base = t * 8;
    int s = 0;
    #pragma unroll
    for (int i = 0; i < 8; i++) s += g_cnt[l][base + i];
    chunk[t] = s;
    __syncthreads();
    for (int o = 1; o < 256; o <<= 1) {
        int v = (t >= o) ? chunk[t - o] : 0;
        __syncthreads();
        chunk[t] += v;
        __syncthreads();
    }
    int run = chunk[t] - s;
    #pragma unroll
    for (int i = 0; i < 8; i++) {
        g_off[l][base + i] = run;
        g_ptr[l][base + i] = run;
        run += g_cnt[l][base + i];
    }
    if (t == 255) g_off[l][Nn] = run;
}

__global__ void norm_scatter3(const int* __restrict__ ei, const float* __restrict__ ew) {
    int l = blockIdx.y;
    int e = blockIdx.x * 256 + threadIdx.x;
    const int* row = ei + l * 2 * Ee;
    const int* col = row + Ee;
    int r = row[e], c = col[e];
    float we = (r == c) ? 0.f : ew[l * Ee + e];
    float dr = g_deg[l][r], dc = g_deg[l][c];
    float ir = dr > 0.f ? rsqrtf(fmaxf(dr, 1e-12f)) : 0.f;
    float ic = dc > 0.f ? rsqrtf(fmaxf(dc, 1e-12f)) : 0.f;
    float nm = -(ir * we * ic);
    g_norm[l][e] = nm;
    atomicAdd(&g_snorm[l][c], nm);
    int pos = atomicAdd(&g_ptr[l][c], 1);
    g_csr[l][pos] = e;
}

// ---------------- normalize: hn(bf16 hi/lo) = (h-m)*r ----------------
__global__ void normalize_k(int slot) {
    float m, r;
    stats_fetch(slot, m, r);
    int i = blockIdx.x * 256 + threadIdx.x;          // over TOT/4
    float4 v = ((const float4*)g_h)[i];
    float4 o;
    o.x = (v.x - m) * r; o.y = (v.y - m) * r; o.z = (v.z - m) * r; o.w = (v.w - m) * r;
    __nv_bfloat162 h0, h1, l0, l1;
    split2(o.x, h0.x, l0.x); split2(o.y, h0.y, l0.y);
    split2(o.z, h1.x, l1.x); split2(o.w, h1.y, l1.y);
    ((__nv_bfloat162*)g_hn_h)[2*i] = h0;  ((__nv_bfloat162*)g_hn_h)[2*i+1] = h1;
    ((__nv_bfloat162*)g_hn_l)[2*i] = l0;  ((__nv_bfloat162*)g_hn_l)[2*i+1] = l1;
}

// ---------------- sparse propagation: one block per node, all 8 batches ----------------
// first=1: tx1[b][n] = r*sum(norm*h[b][row]) - r*m*snorm[n]   (fp32 + hi/lo)
// first=0: tx2[b][n] = 2*sum(norm*tx1[b][row]) - (h[b][n]-m)*r (hi/lo only)
__global__ void prop_all(const int* __restrict__ row, int l, int slot, int first) {
    int n = blockIdx.x;
    int t = threadIdx.x;                    // 64 threads = 64 float4 columns
    int s = g_off[l][n], e = g_off[l][n + 1];
    float m, r;
    stats_fetch(slot, m, r);
    const float4* src = (const float4*)(first ? g_h : g_tx1);
    float4 acc[Bq];
    #pragma unroll
    for (int b = 0; b < Bq; b++) acc[b] = make_float4(0.f, 0.f, 0.f, 0.f);
    __shared__ int   sr[64];
    __shared__ float sn[64];
    for (int base = s; base < e; base += 64) {
        int cnt = min(64, e - base);
        if (t < cnt) {
            int eid = g_csr[l][base + t];
            sr[t] = row[eid];
            sn[t] = g_norm[l][eid];
        }
        __syncthreads();
        for (int j = 0; j < cnt; j++) {
            float nm = sn[j];
            const float4* rp = src + (size_t)sr[j] * 64 + t;
            #pragma unroll
            for (int b = 0; b < Bq; b++) {
                float4 v = __ldg(rp + (size_t)b * Nn * 64);
                acc[b].x += nm * v.x; acc[b].y += nm * v.y;
                acc[b].z += nm * v.z; acc[b].w += nm * v.w;
            }
        }
        __syncthreads();
    }
    float sub = first ? (r * m * g_snorm[l][n]) : 0.f;
    #pragma unroll
    for (int b = 0; b < Bq; b++) {
        size_t di = (size_t)(b * Nn + n) * 64 + t;
        float4 o;
        bf16 *dh, *dl;
        if (first) {
            o.x = r * acc[b].x - sub; o.y = r * acc[b].y - sub;
            o.z = r * acc[b].z - sub; o.w = r * acc[b].w - sub;
            ((float4*)g_tx1)[di] = o;
            dh = g_tx1_h; dl = g_tx1_l;
        } else {
            float4 hv = __ldg(&((const float4*)g_h)[di]);
            o.x = 2.f * acc[b].x - (hv.x - m) * r;
            o.y = 2.f * acc[b].y - (hv.y - m) * r;
            o.z = 2.f * acc[b].z - (hv.z - m) * r;
            o.w = 2.f * acc[b].w - (hv.w - m) * r;
            dh = g_tx2_h; dl = g_tx2_l;
        }
        __nv_bfloat162 h0, h1, l0, l1;
        split2(o.x, h0.x, l0.x); split2(o.y, h0.y, l0.y);
        split2(o.z, h1.x, l1.x); split2(o.w, h1.y, l1.y);
        ((__nv_bfloat162*)dh)[2*di] = h0;  ((__nv_bfloat162*)dh)[2*di+1] = h1;
        ((__nv_bfloat162*)dl)[2*di] = l0;  ((__nv_bfloat162*)dl)[2*di+1] = l1;
    }
}

// ---------------- tensor-core GEMM (bf16 split, 3 passes) ----------------
#define GBM 128
#define GBN 64
#define GBK 64
#define APAD 72   // 64 + 8 bf16 (keeps 16B alignment)

__device__ __forceinline__ uint32_t smem_u32(const void* p) {
    return (uint32_t)__cvta_generic_to_shared(p);
}
__device__ __forceinline__ void ldm_x4(uint32_t* r, uint32_t a) {
    asm volatile("ldmatrix.sync.aligned.m8n8.x4.shared.b16 {%0,%1,%2,%3}, [%4];"
                 : "=r"(r[0]), "=r"(r[1]), "=r"(r[2]), "=r"(r[3]) : "r"(a));
}
__device__ __forceinline__ void ldm_x4_t(uint32_t* r, uint32_t a) {
    asm volatile("ldmatrix.sync.aligned.m8n8.x4.trans.shared.b16 {%0,%1,%2,%3}, [%4];"
                 : "=r"(r[0]), "=r"(r[1]), "=r"(r[2]), "=r"(r[3]) : "r"(a));
}
__device__ __forceinline__ void mma16816(float* d, const uint32_t* a, const uint32_t* b) {
    asm volatile("mma.sync.aligned.m16n8k16.row.col.f32.bf16.bf16.f32 "
                 "{%0,%1,%2,%3},{%4,%5,%6,%7},{%8,%9},{%0,%1,%2,%3};"
                 : "+f"(d[0]), "+f"(d[1]), "+f"(d[2]), "+f"(d[3])
                 : "r"(a[0]), "r"(a[1]), "r"(a[2]), "r"(a[3]), "r"(b[0]), "r"(b[1]));
}

__device__ __forceinline__ float gelu_exact(float v) {
    return 0.5f * v * (1.f + erff(v * 0.70710678118654752f));
}

template<int MODE>
__device__ __forceinline__ void stage_src(int s, int l, const bf16*& Ap, const bf16*& Wp, int& kc) {
    int seg, pass;
    if (MODE == 0) { seg = s / 12; int rr = s % 12; pass = rr >> 2; kc = rr & 3; }
    else           { seg = 0;      int rr = s;      pass = rr >> 2; kc = rr & 3; }
    if (MODE == 0) {
        const bf16* Aarr[6] = { g_hn_h, g_hn_l, g_tx1_h, g_tx1_l, g_tx2_h, g_tx2_l };
        Ap = Aarr[seg * 2 + (pass == 1)];
        Wp = ((pass == 2) ? g_wch_l : g_wch_h) + (size_t)(l * 3 + seg) * Cc * Cc;
    } else {
        Ap = (pass == 1) ? g_hn_l : g_hn_h;
        Wp = ((pass == 2) ? g_wml_l : g_wml_h) + (size_t)l * Cc * Cc;
    }
}

template<int MODE>
__global__ __launch_bounds__(256, 2) void tc_gemm(int l, const float* __restrict__ bias, int slot) {
    extern __shared__ __align__(16) char smem_raw[];
    bf16 (*As)[GBM][APAD] = (bf16 (*)[GBM][APAD])smem_raw;                       // [2][128][72]
    bf16 (*Bs)[GBK][APAD] = (bf16 (*)[GBK][APAD])(smem_raw + 2*GBM*APAD*2);      // [2][64][72]

    const int m0 = blockIdx.x * GBM, n0 = blockIdx.y * GBN;
    const int tid = threadIdx.x;
    const int wid = tid >> 5, lane = tid & 31;
    const int wm = wid >> 1, wn = wid & 1;           // warp tile: 32x32
    const int lrow = lane & 15, lsel = lane >> 4;

    const int NST = (MODE == 0) ? 36 : 12;

    const int ar_[4] = { (tid + 0) >> 3, (tid + 256) >> 3, (tid + 512) >> 3, (tid + 768) >> 3 };
    const int ac_ = (tid & 7) * 8;
    const int br_[2] = { (tid + 0) >> 3, (tid + 256) >> 3 };

    float acc[2][4][4] = {};

    uint4 pa[4], pb[2];
    {
        const bf16 *Ap, *Wp; int kc;
        stage_src<MODE>(0, l, Ap, Wp, kc);
        #pragma unroll
        for (int i = 0; i < 4; i++)
            pa[i] = *(const uint4*)(Ap + (size_t)(m0 + ar_[i]) * Cc + kc * GBK + ac_);
        #pragma unroll
        for (int i = 0; i < 2; i++)
            pb[i] = *(const uint4*)(Wp + (size_t)(kc * GBK + br_[i]) * Cc + n0 + ac_);
        #pragma unroll
        for (int i = 0; i < 4; i++) *(uint4*)&As[0][ar_[i]][ac_] = pa[i];
        #pragma unroll
        for (int i = 0; i < 2; i++) *(uint4*)&Bs[0][br_[i]][ac_] = pb[i];
    }
    __syncthreads();

    for (int s = 0; s < NST; s++) {
        int cur = s & 1;
        if (s + 1 < NST) {
            const bf16 *Ap, *Wp; int kc;
            stage_src<MODE>(s + 1, l, Ap, Wp, kc);
            #pragma unroll
            for (int i = 0; i < 4; i++)
                pa[i] = *(const uint4*)(Ap + (size_t)(m0 + ar_[i]) * Cc + kc * GBK + ac_);
            #pragma unroll
            for (int i = 0; i < 2; i++)
                pb[i] = *(const uint4*)(Wp + (size_t)(kc * GBK + br_[i]) * Cc + n0 + ac_);
        }
        #pragma unroll
        for (int ks = 0; ks < 4; ks++) {
            uint32_t af[2][4], bfr[2][4];
            #pragma unroll
            for (int mt = 0; mt < 2; mt++)
                ldm_x4(af[mt], smem_u32(&As[cur][wm * 32 + mt * 16 + lrow][ks * 16 + lsel * 8]));
            #pragma unroll
            for (int nt2 = 0; nt2 < 2; nt2++)
                ldm_x4_t(bfr[nt2], smem_u32(&Bs[cur][ks * 16 + lrow][wn * 32 + nt2 * 16 + lsel * 8]));
            #pragma unroll
            for (int mt = 0; mt < 2; mt++)
                #pragma unroll
                for (int nt = 0; nt < 4; nt++)
                    mma16816(acc[mt][nt], af[mt], &bfr[nt >> 1][(nt & 1) * 2]);
        }
        if (s + 1 < NST) {
            int nxt = (s + 1) & 1;
            #pragma unroll
            for (int i = 0; i < 4; i++) *(uint4*)&As[nxt][ar_[i]][ac_] = pa[i];
            #pragma unroll
            for (int i = 0; i < 2; i++) *(uint4*)&Bs[nxt][br_[i]][ac_] = pb[i];
            __syncthreads();
        }
    }

    // epilogue: h += ... ; accumulate LN stats of the NEW h into slot
    float ls = 0.f, lq = 0.f;
    const int grp = lane >> 2, qc = lane & 3;
    #pragma unroll
    for (int mt = 0; mt < 2; mt++) {
        #pragma unroll
        for (int nt = 0; nt < 4; nt++) {
            int r0 = m0 + wm * 32 + mt * 16 + grp;
            int c0 = n0 + wn * 32 + nt * 8 + qc * 2;
            float b0 = bias[c0], b1 = bias[c0 + 1];
            #pragma unroll
            for (int hh = 0; hh < 2; hh++) {
                int r = r0 + hh * 8;
                float2* hp = (float2*)(g_h + (size_t)r * Cc + c0);
                float2 hv = *hp;
                float v0 = acc[mt][nt][hh * 2 + 0] + b0;
                float v1 = acc[mt][nt][hh * 2 + 1] + b1;
                if (MODE == 0) { hv.x += v0; hv.y += v1; }
                else           { hv.x += gelu_exact(v0); hv.y += gelu_exact(v1); }
                *hp = hv;
                ls += hv.x + hv.y;
                lq += hv.x * hv.x + hv.y * hv.y;
            }
        }
    }
    __syncthreads();   // reuse of shared for stats after mainloop smem use
    stats_commit(ls, lq, slot);
}

// ---------------- final mean over nodes ----------------
__global__ void zero_out(float* __restrict__ out) {
    int i = blockIdx.x * 256 + threadIdx.x;
    if (i < Bq * Cc) out[i] = 0.f;
}

__global__ void mean_k(float* __restrict__ out) {
    int b = blockIdx.x, chunk = blockIdx.y;
    int c = threadIdx.x;
    float s = 0.f;
    int nb = chunk * 128;
    const float* base = g_h + (size_t)b * Nn * Cc + c;
    for (int n = nb; n < nb + 128; n++) s += base[(size_t)n * Cc];
    atomicAdd(&out[b * Cc + c], s * (1.f / (float)Nn));
}

// ---------------- launch ----------------
extern "C" void kernel_launch(void* const* d_in, const int* in_sizes, int n_in,
                              void* d_out, int out_size) {
    const float* nf = (const float*)d_in[0];   // node_feature [8,2048,256]
    const float* ew = (const float*)d_in[1];   // edge_weight  [3,32768]
    const float* cw = (const float*)d_in[2];   // cheb_w [3,3,256,256]
    const float* cb = (const float*)d_in[3];   // cheb_b [3,256]
    const float* mw = (const float*)d_in[4];   // mlp_w  [3,256,256]
    const float* mb = (const float*)d_in[5];   // mlp_b  [3,256]
    const int*   ei = (const int*)d_in[6];     // edge_index [3,2,32768]
    float* out = (float*)d_out;                // [8,256]

    const int SMEM = 2 * GBM * APAD * 2 + 2 * GBK * APAD * 2;   // 55296 B
    cudaFuncSetAttribute(tc_gemm<0>, cudaFuncAttributeMaxDynamicSharedMemorySize, SMEM);
    cudaFuncSetAttribute(tc_gemm<1>, cudaFuncAttributeMaxDynamicSharedMemorySize, SMEM);

    zero_sred<<<1, 32>>>();
    copy_init<<<TOT / 1024, 256>>>(nf);        // stats -> slot 0
    split_w<<<(3 * 3 * Cc * Cc + 255) / 256, 256>>>(cw, mw);

    // CSR + edge norm for all 3 layers (constant across layers)
    zero_small3<<<(3 * Nn + 255) / 256, 256>>>();
    deg_count3<<<dim3(Ee / 256, 3), 256>>>(ei, ew);
    scan3<<<3, 256>>>();
    norm_scatter3<<<dim3(Ee / 256, 3), 256>>>(ei, ew);

    for (int l = 0; l < 3; l++) {
        const int* row = ei + l * 2 * Ee;
        int slotA = 2 * l;        // stats for LN before cheb
        int slotB = 2 * l + 1;    // stats for LN before mlp (written by cheb gemm)
        int slotC = 2 * l + 2;    // stats for next layer (written by mlp gemm)

        // LN -> hn bf16 hi/lo
        normalize_k<<<TOT / 1024, 256>>>(slotA);

        // Chebyshev props (gather, all batches per block)
        prop_all<<<Nn, 64>>>(row, l, slotA, 1);   // tx1
        prop_all<<<Nn, 64>>>(row, l, slotA, 0);   // tx2

        // tensor-core Cheb GEMM + bias + residual (+ stats -> slotB)
        tc_gemm<0><<<dim3(Mr / GBM, Cc / GBN), 256, SMEM>>>(l, cb + l * Cc, slotB);

        // LN -> hn
        normalize_k<<<TOT / 1024, 256>>>(slotB);

        // tensor-core MLP + GELU + residual (+ stats -> slotC)
        tc_gemm<1><<<dim3(Mr / GBM, Cc / GBN), 256, SMEM>>>(l, mb + l * Cc, slotC);
    }
    zero_out<<<8, 256>>>(out);
    mean_k<<<dim3(Bq, 16), 256>>>(out);
}

// round 11
// speedup vs baseline: 2.4750x; 1.2998x over previous
#include <cuda_runtime.h>
#include <cuda_bf16.h>
#include <math.h>
#include <stdint.h>

#define Bq 8
#define Nn 2048
#define Cc 256
#define Ee 32768
#define TOT (Bq*Nn*Cc)      // 4194304
#define Mr  (Bq*Nn)         // 16384

typedef __nv_bfloat16 bf16;

// Persistent scratch (device globals; no allocations allowed)
__device__ __align__(16) float g_h0[TOT];
__device__ __align__(16) float g_h1[TOT];
__device__ __align__(16) float g_tx1[TOT];
__device__ __align__(16) bf16  g_tx1_h[TOT], g_tx1_l[TOT];
__device__ __align__(16) bf16  g_tx2_h[TOT], g_tx2_l[TOT];
__device__ __align__(16) bf16  g_wch_h[3*3*Cc*Cc], g_wch_l[3*3*Cc*Cc];
__device__ __align__(16) bf16  g_wml_h[3*Cc*Cc],   g_wml_l[3*Cc*Cc];
__device__ float g_deg[3][Nn];
__device__ float g_norm[3][Ee];
__device__ float g_snorm[3][Nn];   // per-node sum of norm (incoming)
__device__ float g_sred[14];       // 7 slots x {sum, sumsq}
// CSR by destination (col), per layer
__device__ int g_cnt[3][Nn];
__device__ int g_off[3][Nn + 1];
__device__ int g_ptr[3][Nn];
__device__ int g_csr[3][Ee];

__device__ __forceinline__ void split2(float x, bf16& h, bf16& l) {
    h = __float2bfloat16(x);
    l = __float2bfloat16(x - __bfloat162float(h));
}

// block-reduce (ls,lq) over 256 threads and atomically add into slot
__device__ __forceinline__ void stats_commit(float ls, float lq, int slot) {
    int lane = threadIdx.x & 31, wid = threadIdx.x >> 5;
    #pragma unroll
    for (int o = 16; o > 0; o >>= 1) {
        ls += __shfl_xor_sync(0xffffffffu, ls, o);
        lq += __shfl_xor_sync(0xffffffffu, lq, o);
    }
    __shared__ float ws[8], wq[8];
    if (lane == 0) { ws[wid] = ls; wq[wid] = lq; }
    __syncthreads();
    if (threadIdx.x == 0) {
        float s = 0.f, q = 0.f;
        #pragma unroll
        for (int i = 0; i < 8; i++) { s += ws[i]; q += wq[i]; }
        atomicAdd(&g_sred[slot * 2 + 0], s);
        atomicAdd(&g_sred[slot * 2 + 1], q);
    }
}

__device__ __forceinline__ void stats_fetch(int slot, float& m, float& r) {
    float s = g_sred[slot * 2 + 0], q = g_sred[slot * 2 + 1];
    m = s / (float)TOT;
    float var = q / (float)TOT - m * m;
    r = rsqrtf(var + 1e-5f);
}

// ---------------- init ----------------
__global__ void zero_sred() {
    if (threadIdx.x < 14) g_sred[threadIdx.x] = 0.f;
}

__global__ void copy_init(const float* __restrict__ x) {
    int i = blockIdx.x * 256 + threadIdx.x;          // over TOT/4
    float4 v = ((const float4*)x)[i];
    ((float4*)g_h0)[i] = v;
    float ls = (v.x + v.y) + (v.z + v.w);
    float lq = v.x*v.x + v.y*v.y + v.z*v.z + v.w*v.w;
    stats_commit(ls, lq, 0);
}

// split weights once per launch
__global__ void split_w(const float* __restrict__ cw, const float* __restrict__ mw) {
    int i = blockIdx.x * 256 + threadIdx.x;
    int NC = 3 * 3 * Cc * Cc;
    if (i < NC) split2(cw[i], g_wch_h[i], g_wch_l[i]);
    if (i < 3 * Cc * Cc) split2(mw[i], g_wml_h[i], g_wml_l[i]);
}

// ---------------- CSR build (all 3 layers, once per launch) ----------------
__global__ void zero_small3() {
    int i = blockIdx.x * 256 + threadIdx.x;          // over 3*Nn
    if (i < 3 * Nn) {
        ((float*)g_deg)[i] = 0.f;
        ((float*)g_snorm)[i] = 0.f;
        ((int*)g_cnt)[i] = 0;
    }
}

__global__ void deg_count3(const int* __restrict__ ei, const float* __restrict__ ew) {
    int l = blockIdx.y;
    int e = blockIdx.x * 256 + threadIdx.x;
    const int* row = ei + l * 2 * Ee;
    const int* col = row + Ee;
    int r = row[e], c = col[e];
    float we = (r == c) ? 0.f : ew[l * Ee + e];
    atomicAdd(&g_deg[l][r], we);
    atomicAdd(&g_cnt[l][c], 1);
}

__global__ void scan3() {
    int l = blockIdx.x;
    __shared__ int chunk[256];
    int t = threadIdx.x;
    int base = t * 8;
    int s = 0;
    #pragma unroll
    for (int i = 0; i < 8; i++) s += g_cnt[l][base + i];
    chunk[t] = s;
    __syncthreads();
    for (int o = 1; o < 256; o <<= 1) {
        int v = (t >= o) ? chunk[t - o] : 0;
        __syncthreads();
        chunk[t] += v;
        __syncthreads();
    }
    int run = chunk[t] - s;
    #pragma unroll
    for (int i = 0; i < 8; i++) {
        g_off[l][base + i] = run;
        g_ptr[l][base + i] = run;
        run += g_cnt[l][base + i];
    }
    if (t == 255) g_off[l][Nn] = run;
}

__global__ void norm_scatter3(const int* __restrict__ ei, const float* __restrict__ ew) {
    int l = blockIdx.y;
    int e = blockIdx.x * 256 + threadIdx.x;
    const int* row = ei + l * 2 * Ee;
    const int* col = row + Ee;
    int r = row[e], c = col[e];
    float we = (r == c) ? 0.f : ew[l * Ee + e];
    float dr = g_deg[l][r], dc = g_deg[l][c];
    float ir = dr > 0.f ? rsqrtf(fmaxf(dr, 1e-12f)) : 0.f;
    float ic = dc > 0.f ? rsqrtf(fmaxf(dc, 1e-12f)) : 0.f;
    float nm = -(ir * we * ic);
    g_norm[l][e] = nm;
    atomicAdd(&g_snorm[l][c], nm);
    int pos = atomicAdd(&g_ptr[l][c], 1);
    g_csr[l][pos] = e;
}

// ---------------- sparse propagation: one block per (node, batch-half) ----------------
// first=1: tx1[b][n] = r*sum(norm*h[b][row]) - r*m*snorm[n]   (fp32 + hi/lo)
// first=0: tx2[b][n] = 2*sum(norm*tx1[b][row]) - (h[b][n]-m)*r (hi/lo only)
__global__ void prop_all(const int* __restrict__ row, int l, int slot, int first, int cur) {
    const float* hsrc = cur ? g_h1 : g_h0;
    int n = blockIdx.x;
    int b0 = blockIdx.y * 4;
    int t = threadIdx.x;                    // 64 threads = 64 float4 columns
    int s = g_off[l][n], e = g_off[l][n + 1];
    float m, r;
    stats_fetch(slot, m, r);
    const float4* src = (const float4*)(first ? hsrc : g_tx1);
    float4 acc[4];
    #pragma unroll
    for (int b = 0; b < 4; b++) acc[b] = make_float4(0.f, 0.f, 0.f, 0.f);
    __shared__ int   sr[64];
    __shared__ float sn[64];
    for (int base = s; base < e; base += 64) {
        int cnt = min(64, e - base);
        if (t < cnt) {
            int eid = g_csr[l][base + t];
            sr[t] = row[eid];
            sn[t] = g_norm[l][eid];
        }
        __syncthreads();
        for (int j = 0; j < cnt; j++) {
            float nm = sn[j];
            const float4* rp = src + (size_t)sr[j] * 64 + t + (size_t)b0 * Nn * 64;
            #pragma unroll
            for (int b = 0; b < 4; b++) {
                float4 v = __ldg(rp + (size_t)b * Nn * 64);
                acc[b].x += nm * v.x; acc[b].y += nm * v.y;
                acc[b].z += nm * v.z; acc[b].w += nm * v.w;
            }
        }
        __syncthreads();
    }
    float sub = first ? (r * m * g_snorm[l][n]) : 0.f;
    #pragma unroll
    for (int b = 0; b < 4; b++) {
        size_t di = (size_t)((b0 + b) * Nn + n) * 64 + t;
        float4 o;
        bf16 *dh, *dl;
        if (first) {
            o.x = r * acc[b].x - sub; o.y = r * acc[b].y - sub;
            o.z = r * acc[b].z - sub; o.w = r * acc[b].w - sub;
            ((float4*)g_tx1)[di] = o;
            dh = g_tx1_h; dl = g_tx1_l;
        } else {
            float4 hv = __ldg(&((const float4*)hsrc)[di]);
            o.x = 2.f * acc[b].x - (hv.x - m) * r;
            o.y = 2.f * acc[b].y - (hv.y - m) * r;
            o.z = 2.f * acc[b].z - (hv.z - m) * r;
            o.w = 2.f * acc[b].w - (hv.w - m) * r;
            dh = g_tx2_h; dl = g_tx2_l;
        }
        __nv_bfloat162 h0, h1, l0, l1;
        split2(o.x, h0.x, l0.x); split2(o.y, h0.y, l0.y);
        split2(o.z, h1.x, l1.x); split2(o.w, h1.y, l1.y);
        ((__nv_bfloat162*)dh)[2*di] = h0;  ((__nv_bfloat162*)dh)[2*di+1] = h1;
        ((__nv_bfloat162*)dl)[2*di] = l0;  ((__nv_bfloat162*)dl)[2*di+1] = l1;
    }
}

// ---------------- tensor-core GEMM (bf16 split, inline LN, 3 passes/tile) ----------------
// Ping-pong: read ALL inputs from h[cur], write new h to h[1-cur]. No RW race.
// MODE 0: hout = hin + (hn@W0 + tx1@W1 + tx2@W2) + bias   (hn inline from hin)
// MODE 1: hout = hin + gelu(hn@W + bias)

#define GBM 128
#define GBN 64
#define GBK 64
#define APAD 72   // 64 + 8 bf16 (keeps 16B alignment)

__device__ __forceinline__ uint32_t smem_u32(const void* p) {
    return (uint32_t)__cvta_generic_to_shared(p);
}
__device__ __forceinline__ void ldm_x4(uint32_t* r, uint32_t a) {
    asm volatile("ldmatrix.sync.aligned.m8n8.x4.shared.b16 {%0,%1,%2,%3}, [%4];"
                 : "=r"(r[0]), "=r"(r[1]), "=r"(r[2]), "=r"(r[3]) : "r"(a));
}
__device__ __forceinline__ void ldm_x4_t(uint32_t* r, uint32_t a) {
    asm volatile("ldmatrix.sync.aligned.m8n8.x4.trans.shared.b16 {%0,%1,%2,%3}, [%4];"
                 : "=r"(r[0]), "=r"(r[1]), "=r"(r[2]), "=r"(r[3]) : "r"(a));
}
__device__ __forceinline__ void mma16816(float* d, const uint32_t* a, const uint32_t* b) {
    asm volatile("mma.sync.aligned.m16n8k16.row.col.f32.bf16.bf16.f32 "
                 "{%0,%1,%2,%3},{%4,%5,%6,%7},{%8,%9},{%0,%1,%2,%3};"
                 : "+f"(d[0]), "+f"(d[1]), "+f"(d[2]), "+f"(d[3])
                 : "r"(a[0]), "r"(a[1]), "r"(a[2]), "r"(a[3]), "r"(b[0]), "r"(b[1]));
}

__device__ __forceinline__ float gelu_exact(float v) {
    return 0.5f * v * (1.f + erff(v * 0.70710678118654752f));
}

// stage -> pointers. seg 0 = hn (fp32 hin, inline normalize); seg 1/2 = tx split arrays.
template<int MODE>
__device__ __forceinline__ void stage_ptrs(int s, int l, int& seg, int& kc,
                                           const bf16*& Ah, const bf16*& Al,
                                           const bf16*& Wh, const bf16*& Wl) {
    seg = (MODE == 0) ? (s >> 2) : 0;
    kc = s & 3;
    if (seg == 1) { Ah = g_tx1_h; Al = g_tx1_l; }
    else if (seg == 2) { Ah = g_tx2_h; Al = g_tx2_l; }
    else { Ah = nullptr; Al = nullptr; }
    if (MODE == 0) {
        Wh = g_wch_h + (size_t)(l * 3 + seg) * Cc * Cc;
        Wl = g_wch_l + (size_t)(l * 3 + seg) * Cc * Cc;
    } else {
        Wh = g_wml_h + (size_t)l * Cc * Cc;
        Wl = g_wml_l + (size_t)l * Cc * Cc;
    }
}

template<int MODE>
__global__ __launch_bounds__(256, 2) void tc_gemm(int l, const float* __restrict__ bias,
                                                  int slotIn, int slotOut, int cur) {
    const float* hin = cur ? g_h1 : g_h0;
    float* hout = cur ? g_h0 : g_h1;

    extern __shared__ __align__(16) char smem_raw[];
    bf16 (*As_h)[APAD] = (bf16 (*)[APAD])smem_raw;                               // [128][72]
    bf16 (*As_l)[APAD] = (bf16 (*)[APAD])(smem_raw + GBM*APAD*2);                // [128][72]
    bf16 (*Bs_h)[APAD] = (bf16 (*)[APAD])(smem_raw + 2*GBM*APAD*2);              // [64][72]
    bf16 (*Bs_l)[APAD] = (bf16 (*)[APAD])(smem_raw + 2*GBM*APAD*2 + GBK*APAD*2); // [64][72]

    const int m0 = blockIdx.x * GBM, n0 = blockIdx.y * GBN;
    const int tid = threadIdx.x;
    const int wid = tid >> 5, lane = tid & 31;
    const int wm = wid >> 1, wn = wid & 1;           // warp tile: 32x32
    const int lrow = lane & 15, lsel = lane >> 4;

    const int NST = (MODE == 0) ? 12 : 4;

    float m, r;
    stats_fetch(slotIn, m, r);

    float acc[2][4][4] = {};
    uint4 pa[8], pb[4];

#define LOAD_STAGE(S)                                                                 \
    {                                                                                 \
        int seg, kc; const bf16 *Ah_, *Al_, *Wh_, *Wl_;                               \
        stage_ptrs<MODE>((S), l, seg, kc, Ah_, Al_, Wh_, Wl_);                        \
        if (seg == 0) {                                                               \
            _Pragma("unroll")                                                         \
            for (int p = 0; p < 8; p++) {                                             \
                int ci = tid + p * 256;                                               \
                int row = ci >> 4, c4 = (ci & 15) * 4;                                \
                pa[p] = *(const uint4*)(hin + (size_t)(m0 + row) * Cc + kc * GBK + c4); \
            }                                                                         \
        } else {                                                                      \
            _Pragma("unroll")                                                         \
            for (int p = 0; p < 4; p++) {                                             \
                int ci = tid + p * 256;                                               \
                int row = ci >> 3, c8 = (ci & 7) * 8;                                 \
                pa[p]     = *(const uint4*)(Ah_ + (size_t)(m0 + row) * Cc + kc * GBK + c8); \
                pa[p + 4] = *(const uint4*)(Al_ + (size_t)(m0 + row) * Cc + kc * GBK + c8); \
            }                                                                         \
        }                                                                             \
        _Pragma("unroll")                                                             \
        for (int p = 0; p < 2; p++) {                                                 \
            int ci = tid + p * 256;                                                   \
            int row = ci >> 3, c8 = (ci & 7) * 8;                                     \
            pb[p]     = *(const uint4*)(Wh_ + (size_t)(kc * GBK + row) * Cc + n0 + c8); \
            pb[p + 2] = *(const uint4*)(Wl_ + (size_t)(kc * GBK + row) * Cc + n0 + c8); \
        }                                                                             \
    }

#define STORE_STAGE(S)                                                                \
    {                                                                                 \
        int seg = (MODE == 0) ? ((S) >> 2) : 0;                                       \
        if (seg == 0) {                                                               \
            _Pragma("unroll")                                                         \
            for (int p = 0; p < 8; p++) {                                             \
                int ci = tid + p * 256;                                               \
                int row = ci >> 4, c4 = (ci & 15) * 4;                                \
                float4 v = *(float4*)&pa[p];                                          \
                bf16 hh[4], ll[4];                                                    \
                split2((v.x - m) * r, hh[0], ll[0]);                                  \
                split2((v.y - m) * r, hh[1], ll[1]);                                  \
                split2((v.z - m) * r, hh[2], ll[2]);                                  \
                split2((v.w - m) * r, hh[3], ll[3]);                                  \
                *(uint2*)&As_h[row][c4] = *(uint2*)hh;                                \
                *(uint2*)&As_l[row][c4] = *(uint2*)ll;                                \
            }                                                                         \
        } else {                                                                      \
            _Pragma("unroll")                                                         \
            for (int p = 0; p < 4; p++) {                                             \
                int ci = tid + p * 256;                                               \
                int row = ci >> 3, c8 = (ci & 7) * 8;                                 \
                *(uint4*)&As_h[row][c8] = pa[p];                                      \
                *(uint4*)&As_l[row][c8] = pa[p + 4];                                  \
            }                                                                         \
        }                                                                             \
        _Pragma("unroll")                                                             \
        for (int p = 0; p < 2; p++) {                                                 \
            int ci = tid + p * 256;                                                   \
            int row = ci >> 3, c8 = (ci & 7) * 8;                                     \
            *(uint4*)&Bs_h[row][c8] = pb[p];                                          \
            *(uint4*)&Bs_l[row][c8] = pb[p + 2];                                      \
        }                                                                             \
    }

    LOAD_STAGE(0);
    STORE_STAGE(0);
    __syncthreads();

    for (int s = 0; s < NST; s++) {
        if (s + 1 < NST) LOAD_STAGE(s + 1);
        #pragma unroll
        for (int ks = 0; ks < 4; ks++) {
            uint32_t ah[2][4], al[2][4], wh[2][4], wl[2][4];
            #pragma unroll
            for (int mt = 0; mt < 2; mt++) {
                ldm_x4(ah[mt], smem_u32(&As_h[wm * 32 + mt * 16 + lrow][ks * 16 + lsel * 8]));
                ldm_x4(al[mt], smem_u32(&As_l[wm * 32 + mt * 16 + lrow][ks * 16 + lsel * 8]));
            }
            #pragma unroll
            for (int nt2 = 0; nt2 < 2; nt2++) {
                ldm_x4_t(wh[nt2], smem_u32(&Bs_h[ks * 16 + lrow][wn * 32 + nt2 * 16 + lsel * 8]));
                ldm_x4_t(wl[nt2], smem_u32(&Bs_l[ks * 16 + lrow][wn * 32 + nt2 * 16 + lsel * 8]));
            }
            #pragma unroll
            for (int mt = 0; mt < 2; mt++)
                #pragma unroll
                for (int nt = 0; nt < 4; nt++) {
                    mma16816(acc[mt][nt], ah[mt], &wh[nt >> 1][(nt & 1) * 2]);
                    mma16816(acc[mt][nt], al[mt], &wh[nt >> 1][(nt & 1) * 2]);
                    mma16816(acc[mt][nt], ah[mt], &wl[nt >> 1][(nt & 1) * 2]);
                }
        }
        __syncthreads();
        if (s + 1 < NST) {
            STORE_STAGE(s + 1);
            __syncthreads();
        }
    }

    // epilogue: hout = hin + ... ; accumulate LN stats of the NEW h into slotOut
    float ls = 0.f, lq = 0.f;
    const int grp = lane >> 2, qc = lane & 3;
    #pragma unroll
    for (int mt = 0; mt < 2; mt++) {
        #pragma unroll
        for (int nt = 0; nt < 4; nt++) {
            int r0 = m0 + wm * 32 + mt * 16 + grp;
            int c0 = n0 + wn * 32 + nt * 8 + qc * 2;
            float b0 = bias[c0], b1 = bias[c0 + 1];
            #pragma unroll
            for (int hh = 0; hh < 2; hh++) {
                int rr = r0 + hh * 8;
                size_t off = (size_t)rr * Cc + c0;
                float2 hv = *(const float2*)(hin + off);
                float v0 = acc[mt][nt][hh * 2 + 0] + b0;
                float v1 = acc[mt][nt][hh * 2 + 1] + b1;
                if (MODE == 0) { hv.x += v0; hv.y += v1; }
                else           { hv.x += gelu_exact(v0); hv.y += gelu_exact(v1); }
                *(float2*)(hout + off) = hv;
                ls += hv.x + hv.y;
                lq += hv.x * hv.x + hv.y * hv.y;
            }
        }
    }
    stats_commit(ls, lq, slotOut);
}

// ---------------- final mean over nodes ----------------
__global__ void zero_out(float* __restrict__ out) {
    int i = blockIdx.x * 256 + threadIdx.x;
    if (i < Bq * Cc) out[i] = 0.f;
}

__global__ void mean_k(float* __restrict__ out) {
    int b = blockIdx.x, chunk = blockIdx.y;
    int c = threadIdx.x;
    float s = 0.f;
    int nb = chunk * 128;
    const float* base = g_h0 + (size_t)b * Nn * Cc + c;
    for (int n = nb; n < nb + 128; n++) s += base[(size_t)n * Cc];
    atomicAdd(&out[b * Cc + c], s * (1.f / (float)Nn));
}

// ---------------- launch ----------------
extern "C" void kernel_launch(void* const* d_in, const int* in_sizes, int n_in,
                              void* d_out, int out_size) {
    const float* nf = (const float*)d_in[0];   // node_feature [8,2048,256]
    const float* ew = (const float*)d_in[1];   // edge_weight  [3,32768]
    const float* cw = (const float*)d_in[2];   // cheb_w [3,3,256,256]
    const float* cb = (const float*)d_in[3];   // cheb_b [3,256]
    const float* mw = (const float*)d_in[4];   // mlp_w  [3,256,256]
    const float* mb = (const float*)d_in[5];   // mlp_b  [3,256]
    const int*   ei = (const int*)d_in[6];     // edge_index [3,2,32768]
    float* out = (float*)d_out;                // [8,256]

    const int SMEM = 2 * GBM * APAD * 2 + 2 * GBK * APAD * 2;   // 55296 B
    cudaFuncSetAttribute(tc_gemm<0>, cudaFuncAttributeMaxDynamicSharedMemorySize, SMEM);
    cudaFuncSetAttribute(tc_gemm<1>, cudaFuncAttributeMaxDynamicSharedMemorySize, SMEM);

    zero_sred<<<1, 32>>>();
    copy_init<<<TOT / 1024, 256>>>(nf);        // h -> g_h0, stats -> slot 0
    split_w<<<(3 * 3 * Cc * Cc + 255) / 256, 256>>>(cw, mw);

    // CSR + edge norm for all 3 layers (constant across layers)
    zero_small3<<<(3 * Nn + 255) / 256, 256>>>();
    deg_count3<<<dim3(Ee / 256, 3), 256>>>(ei, ew);
    scan3<<<3, 256>>>();
    norm_scatter3<<<dim3(Ee / 256, 3), 256>>>(ei, ew);

    int cur = 0;
    for (int l = 0; l < 3; l++) {
        const int* row = ei + l * 2 * Ee;
        int slotA = 2 * l;        // stats of h entering this layer
        int slotB = 2 * l + 1;    // stats after cheb residual
        int slotC = 2 * l + 2;    // stats after mlp residual

        // Chebyshev props (gather; inline normalize via m,r) — read h[cur]
        prop_all<<<dim3(Nn, 2), 64>>>(row, l, slotA, 1, cur);   // tx1
        prop_all<<<dim3(Nn, 2), 64>>>(row, l, slotA, 0, cur);   // tx2

        // Cheb GEMM: read h[cur] (+tx), write h[1-cur]
        tc_gemm<0><<<dim3(Mr / GBM, Cc / GBN), 256, SMEM>>>(l, cb + l * Cc, slotA, slotB, cur);
        cur ^= 1;

        // MLP GEMM: read h[cur], write h[1-cur]
        tc_gemm<1><<<dim3(Mr / GBM, Cc / GBN), 256, SMEM>>>(l, mb + l * Cc, slotB, slotC, cur);
        cur ^= 1;
    }
    // after 6 flips cur == 0: final h in g_h0
    zero_out<<<8, 256>>>(out);
    mean_k<<<dim3(Bq, 16), 256>>>(out);
}